// round 10
// baseline (speedup 1.0000x reference)
#include <cuda_runtime.h>
#include <cstdint>
#include <math.h>

#define S_  1024
#define B_  4
#define H_  768
#define NH_ 12
#define HD_ 64
#define FF_ 3072
#define E_  4
#define T_  4096
#define H3_ 2304
#define PITCH 136           // smem row pitch (words): conflict-free for frag loads
#define SLAB  (16 * PITCH)  // words per operand slab buffer

// ======================= scratch =======================
__device__ float g_ln1[(size_t)T_ * H_];
__device__ float g_qkv[(size_t)T_ * H3_];
__device__ float g_ctx[(size_t)T_ * H_];
__device__ float g_x1 [(size_t)T_ * H_];
__device__ float g_ln2[(size_t)T_ * H_];
__device__ float g_h1 [(size_t)T_ * FF_];
__device__ int   g_eidx[T_];
__device__ float g_prob[T_];
__device__ int   g_perm[T_];
__device__ int   g_off [E_ + 1];

// ======================= tf32 helpers =======================
__device__ __forceinline__ uint32_t tf32hi(float x) {
    uint32_t h;
    asm("cvt.rna.tf32.f32 %0, %1;" : "=r"(h) : "f"(x));
    return h;
}
#define MMAT(d, a, b) \
    asm volatile("mma.sync.aligned.m16n8k8.row.col.f32.tf32.tf32.f32 " \
        "{%0,%1,%2,%3}, {%4,%5,%6,%7}, {%8,%9}, {%0,%1,%2,%3};" \
        : "+f"((d)[0]), "+f"((d)[1]), "+f"((d)[2]), "+f"((d)[3]) \
        : "r"((a)[0]), "r"((a)[1]), "r"((a)[2]), "r"((a)[3]), "r"((b)[0]), "r"((b)[1]))

// ======================= layernorm =======================
__device__ __forceinline__ void ln_row(const float* __restrict__ x, float* __restrict__ y,
                                       const float* __restrict__ w, const float* __restrict__ b) {
    __shared__ float red[2][8];
    int tid = threadIdx.x;
    float v0 = x[tid], v1 = x[tid + 256], v2 = x[tid + 512];
    float s  = v0 + v1 + v2;
    float ss = v0 * v0 + v1 * v1 + v2 * v2;
    for (int o = 16; o; o >>= 1) {
        s  += __shfl_xor_sync(0xffffffffu, s,  o);
        ss += __shfl_xor_sync(0xffffffffu, ss, o);
    }
    if ((tid & 31) == 0) { red[0][tid >> 5] = s; red[1][tid >> 5] = ss; }
    __syncthreads();
    if (tid < 32) {
        float a = (tid < 8) ? red[0][tid] : 0.f;
        float c = (tid < 8) ? red[1][tid] : 0.f;
        for (int o = 4; o; o >>= 1) {
            a += __shfl_xor_sync(0xffffffffu, a, o);
            c += __shfl_xor_sync(0xffffffffu, c, o);
        }
        if (tid == 0) { red[0][0] = a; red[1][0] = c; }
    }
    __syncthreads();
    float mean = red[0][0] * (1.0f / H_);
    float var  = red[1][0] * (1.0f / H_) - mean * mean;
    float inv  = rsqrtf(var + 1e-5f);
    y[tid]       = (v0 - mean) * inv * w[tid]       + b[tid];
    y[tid + 256] = (v1 - mean) * inv * w[tid + 256] + b[tid + 256];
    y[tid + 512] = (v2 - mean) * inv * w[tid + 512] + b[tid + 512];
}

__global__ void k_ln1(const float* __restrict__ hidden,
                      const float* __restrict__ w, const float* __restrict__ b) {
    ln_row(hidden + (size_t)blockIdx.x * H_, g_ln1 + (size_t)blockIdx.x * H_, w, b);
}
__global__ void k_ln2(const float* __restrict__ w, const float* __restrict__ b) {
    ln_row(g_x1 + (size_t)blockIdx.x * H_, g_ln2 + (size_t)blockIdx.x * H_, w, b);
}

// ======================= TF32 tensor-core GEMM (512 threads, 16 warps) ==========
// 128x128 CTA tile, warp grid 4x4, warp tile 32x32, BK=16 (2x k8 mma steps).
// Double-buffered dynamic smem; tf32 split hoisted to store time.
// NT==3: D += Ahi*Bhi + Ahi*Blo + Alo*Bhi (QKV/dense, routing-critical)
// NT==1: D += Ahi*Bhi (MoE, post-routing)
// MODE 0/1: B = W[N][K] (transposed store).  MODE 2/3: B = W[K][N] (direct).
template<int MODE, int KDIM, int NSTR, int NT>
__global__ void __launch_bounds__(512) k_tgemm(const float* __restrict__ Bsrc,
                                               const float* __restrict__ bias,
                                               const float* __restrict__ extra,
                                               float* __restrict__ outp) {
    constexpr bool TRB = (MODE < 2);
    extern __shared__ uint32_t dsm[];
    uint32_t* Ash = dsm;                                    // [2][SLAB]
    uint32_t* Bsh = dsm + 2 * SLAB;                         // [2][SLAB]
    uint32_t* Asl = (NT == 3) ? dsm + 4 * SLAB : dsm;       // [2][SLAB] (NT==3)
    uint32_t* Bsl = (NT == 3) ? dsm + 6 * SLAB : dsm;
    int* sridx = (int*)(dsm + ((NT == 3) ? 8 : 4) * SLAB);  // [128]

    const int tid = threadIdx.x;
    const int n0 = blockIdx.x * 128;
    const int m0 = blockIdx.y * 128;
    const int e  = (MODE >= 2) ? blockIdx.z : 0;

    int beg = 0, cnt = T_;
    if (MODE >= 2) {
        beg = g_off[e]; cnt = g_off[e + 1] - beg;
        if (m0 >= cnt) return;
    }

    const float* Abase = (MODE == 0) ? g_ln1 : (MODE == 1) ? g_ctx
                        : (MODE == 2) ? g_ln2 : g_h1;
    const float* Bbase = Bsrc;
    if (MODE == 2) Bbase += (size_t)e * H_ * FF_;
    if (MODE == 3) Bbase += (size_t)e * FF_ * H_;

    if (MODE >= 2 && tid < 128)
        sridx[tid] = (m0 + tid < cnt) ? g_perm[beg + m0 + tid] : -1;
    if (MODE >= 2) __syncthreads();

    // ---- loaders: one float4 per thread per operand ----
    const int r  = tid >> 2;          // 0..127 (A/B-TRB row)
    const int ac = tid & 3;           // k-chunk
    bool avA = true;
    long grow = m0 + r;
    if (MODE == 2) { int t = sridx[r]; avA = (t >= 0); grow = avA ? t : 0; }
    if (MODE == 3) { avA = (m0 + r < cnt); grow = avA ? (beg + m0 + r) : 0; }
    const float* pA = Abase + (size_t)grow * KDIM + ac * 4;
    const float* pB = nullptr;      // TRB
    const float* pBn = nullptr;     // !TRB
    const int bk = tid >> 5;        // 0..15
    const int bc = tid & 31;        // 0..31
    if (TRB) pB  = Bbase + (size_t)(n0 + r) * KDIM + ac * 4;
    else     pBn = Bbase + (size_t)bk * NSTR + n0 + bc * 4;

    float4 ra, rb;
    const float4 fz = make_float4(0.f, 0.f, 0.f, 0.f);

    auto storeA = [&](int buf) {
        const float* v = (const float*)&ra;
        uint32_t* dsth = Ash + buf * SLAB;
        uint32_t* dstl = Asl + buf * SLAB;
#pragma unroll
        for (int jj = 0; jj < 4; jj++) {
            int j = (jj + ac) & 3;              // bank stagger across ac
            uint32_t h = tf32hi(v[j]);
            dsth[(ac * 4 + j) * PITCH + r] = h;
            if (NT == 3)
                dstl[(ac * 4 + j) * PITCH + r] = tf32hi(v[j] - __uint_as_float(h));
        }
    };
    auto storeB = [&](int buf) {
        const float* v = (const float*)&rb;
        uint32_t* dsth = Bsh + buf * SLAB;
        uint32_t* dstl = Bsl + buf * SLAB;
        if (TRB) {
#pragma unroll
            for (int jj = 0; jj < 4; jj++) {
                int j = (jj + ac) & 3;
                uint32_t h = tf32hi(v[j]);
                dsth[(ac * 4 + j) * PITCH + r] = h;
                if (NT == 3)
                    dstl[(ac * 4 + j) * PITCH + r] = tf32hi(v[j] - __uint_as_float(h));
            }
        } else {
#pragma unroll
            for (int jj = 0; jj < 4; jj++) {
                int j = (jj + bc) & 3;
                uint32_t h = tf32hi(v[j]);
                dsth[bk * PITCH + bc * 4 + j] = h;
                if (NT == 3)
                    dstl[bk * PITCH + bc * 4 + j] = tf32hi(v[j] - __uint_as_float(h));
            }
        }
    };
    auto loadSlab = [&](int kn) {
        ra = avA ? *(const float4*)(pA + kn) : fz;
        if (TRB) rb = *(const float4*)(pB + kn);
        else     rb = *(const float4*)(pBn + (size_t)kn * NSTR);
    };

    // initial: slab 0 -> buf 0
    loadSlab(0);
    storeA(0); storeB(0);
    __syncthreads();

    // ---- fragment coords: 16 warps, warp grid 4x4, warp tile 32x32 ----
    const int wid = tid >> 5, lane = tid & 31;
    const int wm = wid >> 2, wn = wid & 3;
    const int fr = lane >> 2;                // 0..7
    const int fc = lane & 3;                 // 0..3

    float acc[2][4][4] = {};
    int cur = 0;

    for (int k0 = 0; k0 < KDIM; k0 += 16) {
        const bool more = (k0 + 16) < KDIM;
        if (more) loadSlab(k0 + 16);

        const uint32_t* ah_ = Ash + cur * SLAB;
        const uint32_t* al_ = Asl + cur * SLAB;
        const uint32_t* bh_ = Bsh + cur * SLAB;
        const uint32_t* bl_ = Bsl + cur * SLAB;
#pragma unroll
        for (int ks = 0; ks < 2; ks++) {
            const int kofs = ks * 8;
            uint32_t ahi[2][4], alo[2][4];
#pragma unroll
            for (int mi = 0; mi < 2; mi++) {
                const int mb = wm * 32 + mi * 16 + fr;
                ahi[mi][0] = ah_[(kofs + fc    ) * PITCH + mb    ];
                ahi[mi][1] = ah_[(kofs + fc    ) * PITCH + mb + 8];
                ahi[mi][2] = ah_[(kofs + fc + 4) * PITCH + mb    ];
                ahi[mi][3] = ah_[(kofs + fc + 4) * PITCH + mb + 8];
                if (NT == 3) {
                    alo[mi][0] = al_[(kofs + fc    ) * PITCH + mb    ];
                    alo[mi][1] = al_[(kofs + fc    ) * PITCH + mb + 8];
                    alo[mi][2] = al_[(kofs + fc + 4) * PITCH + mb    ];
                    alo[mi][3] = al_[(kofs + fc + 4) * PITCH + mb + 8];
                }
            }
#pragma unroll
            for (int ni = 0; ni < 4; ni++) {
                const int nb = wn * 32 + ni * 8 + fr;
                uint32_t bhi[2], blo[2];
                bhi[0] = bh_[(kofs + fc    ) * PITCH + nb];
                bhi[1] = bh_[(kofs + fc + 4) * PITCH + nb];
                if (NT == 3) {
                    blo[0] = bl_[(kofs + fc    ) * PITCH + nb];
                    blo[1] = bl_[(kofs + fc + 4) * PITCH + nb];
                }
#pragma unroll
                for (int mi = 0; mi < 2; mi++) {
                    MMAT(acc[mi][ni], ahi[mi], bhi);
                    if (NT == 3) {
                        MMAT(acc[mi][ni], ahi[mi], blo);
                        MMAT(acc[mi][ni], alo[mi], bhi);
                    }
                }
            }
        }
        if (more) {
            storeA(cur ^ 1); storeB(cur ^ 1);
            __syncthreads();
            cur ^= 1;
        }
    }

    // ---- epilogue ----
#pragma unroll
    for (int mi = 0; mi < 2; mi++) {
#pragma unroll
        for (int half = 0; half < 2; half++) {
            const int rl = wm * 32 + mi * 16 + fr + half * 8;
            bool valid = true;
            int tkn = 0; float pgate = 0.f;
            if (MODE == 2) valid = (m0 + rl) < cnt;
            if (MODE == 3) { tkn = sridx[rl]; valid = (tkn >= 0); if (valid) pgate = g_prob[tkn]; }
            if (!valid) continue;
#pragma unroll
            for (int ni = 0; ni < 4; ni++) {
                const int n = n0 + wn * 32 + ni * 8 + fc * 2;
                const float v0 = acc[mi][ni][half * 2 + 0];
                const float v1 = acc[mi][ni][half * 2 + 1];
                if (MODE == 0) {
                    size_t o = (size_t)(m0 + rl) * H3_ + n;
                    g_qkv[o]     = v0 + bias[n];
                    g_qkv[o + 1] = v1 + bias[n + 1];
                } else if (MODE == 1) {
                    size_t o = (size_t)(m0 + rl) * H_ + n;
                    g_x1[o]     = extra[o]     + v0 + bias[n];
                    g_x1[o + 1] = extra[o + 1] + v1 + bias[n + 1];
                } else if (MODE == 2) {
                    size_t o = (size_t)(beg + m0 + rl) * FF_ + n;
                    float x0 = v0 + bias[(size_t)e * FF_ + n];
                    float x1 = v1 + bias[(size_t)e * FF_ + n + 1];
                    g_h1[o]     = 0.5f * x0 * (1.0f + erff(x0 * 0.70710678118654752f));
                    g_h1[o + 1] = 0.5f * x1 * (1.0f + erff(x1 * 0.70710678118654752f));
                } else {
                    size_t o = (size_t)tkn * H_ + n;
                    outp[o]     = g_x1[o]     + pgate * (v0 + bias[(size_t)e * H_ + n]);
                    outp[o + 1] = g_x1[o + 1] + pgate * (v1 + bias[(size_t)e * H_ + n + 1]);
                }
            }
        }
    }
}

// smem byte sizes
#define SMEM_NT3 ((8 * SLAB) * 4 + 512)
#define SMEM_NT1 ((4 * SLAB) * 4 + 512)

// ======================= causal flash attention (SIMT fp32, proven) =======================
__global__ void k_attn() {
    extern __shared__ float sm[];
    float* Qs = sm;
    float* KP = sm + 4096;
    float* Vs = sm + 4096 + 4160;
    int qt = blockIdx.x, n = blockIdx.y, b = blockIdx.z;
    int tx = threadIdx.x, ty = threadIdx.y, tid = ty * 16 + tx;
    int q0 = qt * 64;
    const float SCALE = 0.125f;
    {
        int r = tid >> 4, d4 = (tid & 15) * 4;
        for (int rr = r; rr < 64; rr += 16) {
            float4 v = *(const float4*)(g_qkv + ((size_t)(q0 + rr) * B_ + b) * H3_ + n * 192 + d4);
            float* dst = Qs + rr * 64 + d4;
            dst[0] = v.x * SCALE; dst[1] = v.y * SCALE; dst[2] = v.z * SCALE; dst[3] = v.w * SCALE;
        }
    }
    float o[4][4] = {};
    float m_run[4] = {-1e30f, -1e30f, -1e30f, -1e30f};
    float l_run[4] = {0.f, 0.f, 0.f, 0.f};

    for (int j = 0; j <= qt; ++j) {
        __syncthreads();
        int k0 = j * 64;
        {
            int r = tid >> 4, d4 = (tid & 15) * 4;
            for (int rr = r; rr < 64; rr += 16) {
                const float* base = g_qkv + ((size_t)(k0 + rr) * B_ + b) * H3_ + n * 192;
                float4 kv = *(const float4*)(base + 64 + d4);
                KP[rr * 65 + d4 + 0] = kv.x; KP[rr * 65 + d4 + 1] = kv.y;
                KP[rr * 65 + d4 + 2] = kv.z; KP[rr * 65 + d4 + 3] = kv.w;
                float4 vv = *(const float4*)(base + 128 + d4);
                *(float4*)(Vs + rr * 64 + d4) = vv;
            }
        }
        __syncthreads();
        float sacc[4][4] = {};
#pragma unroll 8
        for (int d = 0; d < 64; ++d) {
            float a[4], kr[4];
#pragma unroll
            for (int i = 0; i < 4; i++) a[i]  = Qs[(ty * 4 + i) * 64 + d];
#pragma unroll
            for (int c = 0; c < 4; c++) kr[c] = KP[(tx * 4 + c) * 65 + d];
#pragma unroll
            for (int i = 0; i < 4; i++)
#pragma unroll
                for (int c = 0; c < 4; c++) sacc[i][c] = fmaf(a[i], kr[c], sacc[i][c]);
        }
        if (j == qt) {
#pragma unroll
            for (int i = 0; i < 4; i++)
#pragma unroll
                for (int c = 0; c < 4; c++)
                    if (tx * 4 + c > ty * 4 + i) sacc[i][c] = -1e30f;
        }
        float mx[4], mnew[4], scl[4], rs[4];
#pragma unroll
        for (int i = 0; i < 4; i++) {
            mx[i] = fmaxf(fmaxf(sacc[i][0], sacc[i][1]), fmaxf(sacc[i][2], sacc[i][3]));
            for (int oo = 8; oo; oo >>= 1)
                mx[i] = fmaxf(mx[i], __shfl_xor_sync(0xffffffffu, mx[i], oo));
            mnew[i] = fmaxf(m_run[i], mx[i]);
            scl[i]  = expf(m_run[i] - mnew[i]);
            m_run[i] = mnew[i];
            rs[i] = 0.f;
#pragma unroll
            for (int c = 0; c < 4; c++) {
                sacc[i][c] = expf(sacc[i][c] - mnew[i]);
                rs[i] += sacc[i][c];
            }
            for (int oo = 8; oo; oo >>= 1)
                rs[i] += __shfl_xor_sync(0xffffffffu, rs[i], oo);
            l_run[i] = l_run[i] * scl[i] + rs[i];
#pragma unroll
            for (int c = 0; c < 4; c++) o[i][c] *= scl[i];
        }
        __syncthreads();
#pragma unroll
        for (int i = 0; i < 4; i++)
#pragma unroll
            for (int c = 0; c < 4; c++)
                KP[(ty * 4 + i) * 65 + tx * 4 + c] = sacc[i][c];
        __syncthreads();
#pragma unroll 8
        for (int d = 0; d < 64; ++d) {
            float pi[4], vj[4];
#pragma unroll
            for (int i = 0; i < 4; i++) pi[i] = KP[(ty * 4 + i) * 65 + d];
#pragma unroll
            for (int c = 0; c < 4; c++) vj[c] = Vs[d * 64 + tx * 4 + c];
#pragma unroll
            for (int i = 0; i < 4; i++)
#pragma unroll
                for (int c = 0; c < 4; c++) o[i][c] = fmaf(pi[i], vj[c], o[i][c]);
        }
    }
#pragma unroll
    for (int i = 0; i < 4; i++) {
        float invl = 1.0f / l_run[i];
#pragma unroll
        for (int c = 0; c < 4; c++)
            g_ctx[((size_t)(q0 + ty * 4 + i) * B_ + b) * H_ + n * HD_ + tx * 4 + c] = o[i][c] * invl;
    }
}

// ======================= gate + routing =======================
__global__ void k_gate(const float* __restrict__ gw) {
    int gidx = blockIdx.x * blockDim.x + threadIdx.x;
    int t = gidx >> 5, lane = gidx & 31;
    if (t >= T_) return;
    const float* x = g_ln2 + (size_t)t * H_;
    float s0 = 0, s1 = 0, s2 = 0, s3 = 0;
    for (int h = lane; h < H_; h += 32) {
        float xv = x[h];
        s0 = fmaf(xv, gw[h],          s0);
        s1 = fmaf(xv, gw[H_ + h],     s1);
        s2 = fmaf(xv, gw[2 * H_ + h], s2);
        s3 = fmaf(xv, gw[3 * H_ + h], s3);
    }
    for (int o = 16; o; o >>= 1) {
        s0 += __shfl_xor_sync(0xffffffffu, s0, o);
        s1 += __shfl_xor_sync(0xffffffffu, s1, o);
        s2 += __shfl_xor_sync(0xffffffffu, s2, o);
        s3 += __shfl_xor_sync(0xffffffffu, s3, o);
    }
    if (lane == 0) {
        float l[4] = {s0, s1, s2, s3};
        float mx = fmaxf(fmaxf(l[0], l[1]), fmaxf(l[2], l[3]));
        float ex[4], z = 0.f;
        for (int e = 0; e < 4; e++) { ex[e] = expf(l[e] - mx); z += ex[e]; }
        int best = 0; float bp = ex[0];
        for (int e = 1; e < 4; e++) if (ex[e] > bp) { bp = ex[e]; best = e; }
        g_eidx[t] = best;
        g_prob[t] = bp / z;
    }
}

// single-block counting sort (replaces zero/count/offsets/scatter)
__global__ void k_route() {
    __shared__ int cnt[E_], off[E_], fill[E_];
    int tid = threadIdx.x;   // 1024
    if (tid < E_) cnt[tid] = 0;
    __syncthreads();
    for (int t = tid; t < T_; t += 1024) atomicAdd(&cnt[g_eidx[t]], 1);
    __syncthreads();
    if (tid == 0) {
        int a = 0;
        for (int e = 0; e < E_; e++) { off[e] = a; fill[e] = a; g_off[e] = a; a += cnt[e]; }
        g_off[E_] = a;
    }
    __syncthreads();
    for (int t = tid; t < T_; t += 1024) {
        int p = atomicAdd(&fill[g_eidx[t]], 1);
        g_perm[p] = t;
    }
}

// ======================= launch =======================
extern "C" void kernel_launch(void* const* d_in, const int* in_sizes, int n_in,
                              void* d_out, int out_size) {
    const float* hidden = (const float*)d_in[0];
    const float* ln1w = (const float*)d_in[2];
    const float* ln1b = (const float*)d_in[3];
    const float* qkvw = (const float*)d_in[4];
    const float* qkvb = (const float*)d_in[5];
    const float* dw   = (const float*)d_in[6];
    const float* db   = (const float*)d_in[7];
    const float* ln2w = (const float*)d_in[8];
    const float* ln2b = (const float*)d_in[9];
    const float* gw   = (const float*)d_in[10];
    const float* w1   = (const float*)d_in[11];
    const float* b1   = (const float*)d_in[12];
    const float* w2   = (const float*)d_in[13];
    const float* b2   = (const float*)d_in[14];
    float* out = (float*)d_out;

    cudaFuncSetAttribute(k_attn, cudaFuncAttributeMaxDynamicSharedMemorySize, 49408);
    cudaFuncSetAttribute((const void*)k_tgemm<0, 768, 1, 3>,
                         cudaFuncAttributeMaxDynamicSharedMemorySize, SMEM_NT3);
    cudaFuncSetAttribute((const void*)k_tgemm<1, 768, 1, 3>,
                         cudaFuncAttributeMaxDynamicSharedMemorySize, SMEM_NT3);
    cudaFuncSetAttribute((const void*)k_tgemm<2, 768, FF_, 1>,
                         cudaFuncAttributeMaxDynamicSharedMemorySize, SMEM_NT1);
    cudaFuncSetAttribute((const void*)k_tgemm<3, 3072, H_, 1>,
                         cudaFuncAttributeMaxDynamicSharedMemorySize, SMEM_NT1);

    k_ln1<<<T_, 256>>>(hidden, ln1w, ln1b);
    k_tgemm<0, 768, 1, 3><<<dim3(H3_ / 128, T_ / 128), 512, SMEM_NT3>>>(qkvw, qkvb, nullptr, nullptr);
    k_attn<<<dim3(S_ / 64, NH_, B_), dim3(16, 16), 49408>>>();
    k_tgemm<1, 768, 1, 3><<<dim3(H_ / 128, T_ / 128), 512, SMEM_NT3>>>(dw, db, hidden, nullptr);
    k_ln2<<<T_, 256>>>(ln2w, ln2b);
    k_gate<<<T_ / 4, 128>>>(gw);
    k_route<<<1, 1024>>>();
    k_tgemm<2, 768, FF_, 1><<<dim3(FF_ / 128, T_ / 128, E_), 512, SMEM_NT1>>>(w1, b1, nullptr, nullptr);
    k_tgemm<3, 3072, H_, 1><<<dim3(H_ / 128, T_ / 128, E_), 512, SMEM_NT1>>>(w2, b2, nullptr, out);
}

// round 11
// speedup vs baseline: 1.2709x; 1.2709x over previous
#include <cuda_runtime.h>
#include <cuda_bf16.h>
#include <cstdint>
#include <math.h>

#define S_  1024
#define B_  4
#define H_  768
#define NH_ 12
#define HD_ 64
#define FF_ 3072
#define E_  4
#define T_  4096
#define H3_ 2304
#define PITCH 136           // smem row pitch (words): conflict-free for frag loads
#define SLAB  (16 * PITCH)  // words per operand slab buffer

// ======================= scratch =======================
__device__ float g_ln1[(size_t)T_ * H_];
__device__ float g_qkv[(size_t)T_ * H3_];
__device__ float g_ctx[(size_t)T_ * H_];
__device__ float g_x1 [(size_t)T_ * H_];
__device__ float g_ln2[(size_t)T_ * H_];
__device__ float g_h1 [(size_t)T_ * FF_];
__device__ int   g_eidx[T_];
__device__ float g_prob[T_];
__device__ int   g_perm[T_];
__device__ int   g_off [E_ + 1];

// ======================= mma helpers =======================
__device__ __forceinline__ uint32_t tf32hi(float x) {
    uint32_t h;
    asm("cvt.rna.tf32.f32 %0, %1;" : "=r"(h) : "f"(x));
    return h;
}
__device__ __forceinline__ uint32_t packbf(float a, float b) {
    __nv_bfloat16 x = __float2bfloat16_rn(a), y = __float2bfloat16_rn(b);
    return ((uint32_t)__bfloat16_as_ushort(y) << 16) | __bfloat16_as_ushort(x);
}
#define MMAT(d, a, b) \
    asm volatile("mma.sync.aligned.m16n8k8.row.col.f32.tf32.tf32.f32 " \
        "{%0,%1,%2,%3}, {%4,%5,%6,%7}, {%8,%9}, {%0,%1,%2,%3};" \
        : "+f"((d)[0]), "+f"((d)[1]), "+f"((d)[2]), "+f"((d)[3]) \
        : "r"((a)[0]), "r"((a)[1]), "r"((a)[2]), "r"((a)[3]), "r"((b)[0]), "r"((b)[1]))
#define MMAB(d, a, b) \
    asm volatile("mma.sync.aligned.m16n8k16.row.col.f32.bf16.bf16.f32 " \
        "{%0,%1,%2,%3}, {%4,%5,%6,%7}, {%8,%9}, {%0,%1,%2,%3};" \
        : "+f"((d)[0]), "+f"((d)[1]), "+f"((d)[2]), "+f"((d)[3]) \
        : "r"((a)[0]), "r"((a)[1]), "r"((a)[2]), "r"((a)[3]), "r"((b)[0]), "r"((b)[1]))

// ======================= layernorm =======================
__device__ __forceinline__ void ln_row(const float* __restrict__ x, float* __restrict__ y,
                                       const float* __restrict__ w, const float* __restrict__ b) {
    __shared__ float red[2][8];
    int tid = threadIdx.x;
    float v0 = x[tid], v1 = x[tid + 256], v2 = x[tid + 512];
    float s  = v0 + v1 + v2;
    float ss = v0 * v0 + v1 * v1 + v2 * v2;
    for (int o = 16; o; o >>= 1) {
        s  += __shfl_xor_sync(0xffffffffu, s,  o);
        ss += __shfl_xor_sync(0xffffffffu, ss, o);
    }
    if ((tid & 31) == 0) { red[0][tid >> 5] = s; red[1][tid >> 5] = ss; }
    __syncthreads();
    if (tid < 32) {
        float a = (tid < 8) ? red[0][tid] : 0.f;
        float c = (tid < 8) ? red[1][tid] : 0.f;
        for (int o = 4; o; o >>= 1) {
            a += __shfl_xor_sync(0xffffffffu, a, o);
            c += __shfl_xor_sync(0xffffffffu, c, o);
        }
        if (tid == 0) { red[0][0] = a; red[1][0] = c; }
    }
    __syncthreads();
    float mean = red[0][0] * (1.0f / H_);
    float var  = red[1][0] * (1.0f / H_) - mean * mean;
    float inv  = rsqrtf(var + 1e-5f);
    y[tid]       = (v0 - mean) * inv * w[tid]       + b[tid];
    y[tid + 256] = (v1 - mean) * inv * w[tid + 256] + b[tid + 256];
    y[tid + 512] = (v2 - mean) * inv * w[tid + 512] + b[tid + 512];
}

__global__ void k_ln1(const float* __restrict__ hidden,
                      const float* __restrict__ w, const float* __restrict__ b) {
    ln_row(hidden + (size_t)blockIdx.x * H_, g_ln1 + (size_t)blockIdx.x * H_, w, b);
}
__global__ void k_ln2(const float* __restrict__ w, const float* __restrict__ b) {
    ln_row(g_x1 + (size_t)blockIdx.x * H_, g_ln2 + (size_t)blockIdx.x * H_, w, b);
}

// ======================= tensor-core GEMM (R9 shape: 256 thr, 8 warps, 64x32 warp tile) ==========
// 128x128 CTA tile, double-buffered dynamic smem.
// NT==3: tf32 3-term (err ~2^-21)
// NT==4: bf16 3-term packed-pair (err ~2^-18), HALF the MMA count of NT3 -- QKV/dense
// NT==1: tf32 1-term (err ~2^-11) -- MoE (post-routing)
// MODE 0/1: B = W[N][K] (transposed store).  MODE 2/3: B = W[K][N] (direct).
template<int MODE, int KDIM, int NSTR, int NT>
__global__ void __launch_bounds__(256) k_tgemm(const float* __restrict__ Bsrc,
                                               const float* __restrict__ bias,
                                               const float* __restrict__ extra,
                                               float* __restrict__ outp) {
    constexpr bool TRB = (MODE < 2);
    constexpr bool BF  = (NT == 4);
    constexpr bool HASLO = (NT == 3 || NT == 4);
    constexpr int  BK  = BF ? 32 : 16;           // K elements per slab
    constexpr int  ACW = BF ? 8 : 4;             // K elements per thread chunk
    extern __shared__ uint32_t dsm[];
    uint32_t* Ash = dsm;                                 // [2][SLAB]
    uint32_t* Bsh = dsm + 2 * SLAB;                      // [2][SLAB]
    uint32_t* Asl = HASLO ? dsm + 4 * SLAB : dsm;        // [2][SLAB]
    uint32_t* Bsl = HASLO ? dsm + 6 * SLAB : dsm;
    int* sridx = (int*)(dsm + (HASLO ? 8 : 4) * SLAB);   // [128]

    const int tid = threadIdx.x;
    const int n0 = blockIdx.x * 128;
    const int m0 = blockIdx.y * 128;
    const int e  = (MODE >= 2) ? blockIdx.z : 0;

    int beg = 0, cnt = T_;
    if (MODE >= 2) {
        beg = g_off[e]; cnt = g_off[e + 1] - beg;
        if (m0 >= cnt) return;
    }

    const float* Abase = (MODE == 0) ? g_ln1 : (MODE == 1) ? g_ctx
                        : (MODE == 2) ? g_ln2 : g_h1;
    const float* Bbase = Bsrc;
    if (MODE == 2) Bbase += (size_t)e * H_ * FF_;
    if (MODE == 3) Bbase += (size_t)e * FF_ * H_;

    if (MODE >= 2 && tid < 128)
        sridx[tid] = (m0 + tid < cnt) ? g_perm[beg + m0 + tid] : -1;
    if (MODE >= 2) __syncthreads();

    // ---- loaders: rows r, r+64; k-chunk ac*ACW ----
    const int ar = tid >> 2;          // 0..63
    const int ac = tid & 3;           // 0..3
    const int arows[2] = { ar, ar + 64 };
    const float* pA[2];
    bool avA[2];
#pragma unroll
    for (int i = 0; i < 2; i++) {
        int r = arows[i];
        long grow = m0 + r;
        avA[i] = true;
        if (MODE == 2) { int t = sridx[r]; avA[i] = (t >= 0); grow = avA[i] ? t : 0; }
        if (MODE == 3) { avA[i] = (m0 + r < cnt); grow = avA[i] ? (beg + m0 + r) : 0; }
        pA[i] = Abase + (size_t)grow * KDIM + ac * ACW;
    }
    const float* pB[2];             // TRB
    const float* pBn = nullptr;     // !TRB
    const int bk = tid >> 4;        // 0..15
    const int bc = tid & 15;        // 0..15
    if (TRB) {
#pragma unroll
        for (int i = 0; i < 2; i++)
            pB[i] = Bbase + (size_t)(n0 + arows[i]) * KDIM + ac * ACW;
    } else {
        pBn = Bbase + (size_t)bk * NSTR + n0 + bc * 4;
    }

    float4 ra[2][2], rb[2][2];
    const float4 fz = make_float4(0.f, 0.f, 0.f, 0.f);

    // ---- split+store helpers ----
    auto storeTF = [&](const float4& v4, uint32_t* dsth, uint32_t* dstl, int row) {
        const float* v = (const float*)&v4;
#pragma unroll
        for (int jj = 0; jj < 4; jj++) {
            int j = (jj + ac) & 3;                 // bank stagger
            uint32_t h = tf32hi(v[j]);
            dsth[(ac * 4 + j) * PITCH + row] = h;
            if (NT == 3)
                dstl[(ac * 4 + j) * PITCH + row] = tf32hi(v[j] - __uint_as_float(h));
        }
    };
    auto storeBF = [&](const float4& lo4, const float4& hi4,
                       uint32_t* dsth, uint32_t* dstl, int row) {
        float f[8] = {lo4.x, lo4.y, lo4.z, lo4.w, hi4.x, hi4.y, hi4.z, hi4.w};
#pragma unroll
        for (int jj = 0; jj < 4; jj++) {
            int jp = (jj + ac) & 3;                // bank stagger
            float v0 = f[2 * jp], v1 = f[2 * jp + 1];
            __nv_bfloat16 h0 = __float2bfloat16_rn(v0), h1 = __float2bfloat16_rn(v1);
            float l0 = v0 - __bfloat162float(h0);
            float l1 = v1 - __bfloat162float(h1);
            dsth[(ac * 4 + jp) * PITCH + row] = ((uint32_t)__bfloat16_as_ushort(h1) << 16)
                                              | __bfloat16_as_ushort(h0);
            dstl[(ac * 4 + jp) * PITCH + row] = packbf(l0, l1);
        }
    };
    auto storeAll = [&](int buf) {
        uint32_t* Ah = Ash + buf * SLAB; uint32_t* Al = Asl + buf * SLAB;
        uint32_t* Bh = Bsh + buf * SLAB; uint32_t* Bl = Bsl + buf * SLAB;
#pragma unroll
        for (int i = 0; i < 2; i++) {
            if (BF) storeBF(ra[i][0], ra[i][1], Ah, Al, arows[i]);
            else    storeTF(ra[i][0], Ah, Al, arows[i]);
        }
        if (TRB) {
#pragma unroll
            for (int i = 0; i < 2; i++) {
                if (BF) storeBF(rb[i][0], rb[i][1], Bh, Bl, arows[i]);
                else    storeTF(rb[i][0], Bh, Bl, arows[i]);
            }
        } else {
            // !TRB only used with NT==1 (tf32, 16-k slab): direct [k][n] store
#pragma unroll
            for (int i = 0; i < 2; i++) {
                const float* v = (const float*)&rb[i][0];
#pragma unroll
                for (int jj = 0; jj < 4; jj++) {
                    int j = (jj + bc) & 3;
                    Bh[bk * PITCH + bc * 4 + i * 64 + j] = tf32hi(v[j]);
                }
            }
        }
    };
    auto loadSlab = [&](int kn) {
#pragma unroll
        for (int i = 0; i < 2; i++) {
            ra[i][0] = avA[i] ? *(const float4*)(pA[i] + kn) : fz;
            if (BF) ra[i][1] = avA[i] ? *(const float4*)(pA[i] + kn + 4) : fz;
            if (TRB) {
                rb[i][0] = *(const float4*)(pB[i] + kn);
                if (BF) rb[i][1] = *(const float4*)(pB[i] + kn + 4);
            }
        }
        if (!TRB) {
            rb[0][0] = *(const float4*)(pBn + (size_t)kn * NSTR);
            rb[1][0] = *(const float4*)(pBn + (size_t)kn * NSTR + 64);
        }
    };

    loadSlab(0);
    storeAll(0);
    __syncthreads();

    // ---- fragment coords: 8 warps (2x4), warp tile 64x32 ----
    const int wid = tid >> 5, lane = tid & 31;
    const int wm = wid >> 2, wn = wid & 3;
    const int fr = lane >> 2;                // 0..7
    const int fc = lane & 3;                 // 0..3

    float acc[4][4][4] = {};
    int cur = 0;

    for (int k0 = 0; k0 < KDIM; k0 += BK) {
        const bool more = (k0 + BK) < KDIM;
        if (more) loadSlab(k0 + BK);

        const uint32_t* ah_ = Ash + cur * SLAB;
        const uint32_t* al_ = Asl + cur * SLAB;
        const uint32_t* bh_ = Bsh + cur * SLAB;
        const uint32_t* bl_ = Bsl + cur * SLAB;
#pragma unroll
        for (int ks = 0; ks < 2; ks++) {
            const int kofs = ks * 8;             // word offset (same for tf32 k8 / bf16 k16)
            uint32_t ahi[4][4], alo[4][4];
#pragma unroll
            for (int mi = 0; mi < 4; mi++) {
                const int mb = wm * 64 + mi * 16 + fr;
                ahi[mi][0] = ah_[(kofs + fc    ) * PITCH + mb    ];
                ahi[mi][1] = ah_[(kofs + fc    ) * PITCH + mb + 8];
                ahi[mi][2] = ah_[(kofs + fc + 4) * PITCH + mb    ];
                ahi[mi][3] = ah_[(kofs + fc + 4) * PITCH + mb + 8];
                if (HASLO) {
                    alo[mi][0] = al_[(kofs + fc    ) * PITCH + mb    ];
                    alo[mi][1] = al_[(kofs + fc    ) * PITCH + mb + 8];
                    alo[mi][2] = al_[(kofs + fc + 4) * PITCH + mb    ];
                    alo[mi][3] = al_[(kofs + fc + 4) * PITCH + mb + 8];
                }
            }
#pragma unroll
            for (int ni = 0; ni < 4; ni++) {
                const int nb = wn * 32 + ni * 8 + fr;
                uint32_t bhi[2], blo[2];
                bhi[0] = bh_[(kofs + fc    ) * PITCH + nb];
                bhi[1] = bh_[(kofs + fc + 4) * PITCH + nb];
                if (HASLO) {
                    blo[0] = bl_[(kofs + fc    ) * PITCH + nb];
                    blo[1] = bl_[(kofs + fc + 4) * PITCH + nb];
                }
#pragma unroll
                for (int mi = 0; mi < 4; mi++) {
                    if (BF) {
                        MMAB(acc[mi][ni], ahi[mi], bhi);
                        MMAB(acc[mi][ni], ahi[mi], blo);
                        MMAB(acc[mi][ni], alo[mi], bhi);
                    } else {
                        MMAT(acc[mi][ni], ahi[mi], bhi);
                        if (NT == 3) {
                            MMAT(acc[mi][ni], ahi[mi], blo);
                            MMAT(acc[mi][ni], alo[mi], bhi);
                        }
                    }
                }
            }
        }
        if (more) {
            storeAll(cur ^ 1);
            __syncthreads();
            cur ^= 1;
        }
    }

    // ---- epilogue (C frag identical for k8/k16 shapes) ----
#pragma unroll
    for (int mi = 0; mi < 4; mi++) {
#pragma unroll
        for (int half = 0; half < 2; half++) {
            const int rl = wm * 64 + mi * 16 + fr + half * 8;
            bool valid = true;
            int tkn = 0; float pgate = 0.f;
            if (MODE == 2) valid = (m0 + rl) < cnt;
            if (MODE == 3) { tkn = sridx[rl]; valid = (tkn >= 0); if (valid) pgate = g_prob[tkn]; }
            if (!valid) continue;
#pragma unroll
            for (int ni = 0; ni < 4; ni++) {
                const int n = n0 + wn * 32 + ni * 8 + fc * 2;
                const float v0 = acc[mi][ni][half * 2 + 0];
                const float v1 = acc[mi][ni][half * 2 + 1];
                if (MODE == 0) {
                    size_t o = (size_t)(m0 + rl) * H3_ + n;
                    g_qkv[o]     = v0 + bias[n];
                    g_qkv[o + 1] = v1 + bias[n + 1];
                } else if (MODE == 1) {
                    size_t o = (size_t)(m0 + rl) * H_ + n;
                    g_x1[o]     = extra[o]     + v0 + bias[n];
                    g_x1[o + 1] = extra[o + 1] + v1 + bias[n + 1];
                } else if (MODE == 2) {
                    size_t o = (size_t)(beg + m0 + rl) * FF_ + n;
                    float x0 = v0 + bias[(size_t)e * FF_ + n];
                    float x1 = v1 + bias[(size_t)e * FF_ + n + 1];
                    g_h1[o]     = 0.5f * x0 * (1.0f + erff(x0 * 0.70710678118654752f));
                    g_h1[o + 1] = 0.5f * x1 * (1.0f + erff(x1 * 0.70710678118654752f));
                } else {
                    size_t o = (size_t)tkn * H_ + n;
                    outp[o]     = g_x1[o]     + pgate * (v0 + bias[(size_t)e * H_ + n]);
                    outp[o + 1] = g_x1[o + 1] + pgate * (v1 + bias[(size_t)e * H_ + n + 1]);
                }
            }
        }
    }
}

// smem byte sizes
#define SMEM_HASLO ((8 * SLAB) * 4 + 512)
#define SMEM_NT1   ((4 * SLAB) * 4 + 512)

// ======================= causal flash attention (SIMT fp32, proven) =======================
__global__ void k_attn() {
    extern __shared__ float sm[];
    float* Qs = sm;
    float* KP = sm + 4096;
    float* Vs = sm + 4096 + 4160;
    int qt = blockIdx.x, n = blockIdx.y, b = blockIdx.z;
    int tx = threadIdx.x, ty = threadIdx.y, tid = ty * 16 + tx;
    int q0 = qt * 64;
    const float SCALE = 0.125f;
    {
        int r = tid >> 4, d4 = (tid & 15) * 4;
        for (int rr = r; rr < 64; rr += 16) {
            float4 v = *(const float4*)(g_qkv + ((size_t)(q0 + rr) * B_ + b) * H3_ + n * 192 + d4);
            float* dst = Qs + rr * 64 + d4;
            dst[0] = v.x * SCALE; dst[1] = v.y * SCALE; dst[2] = v.z * SCALE; dst[3] = v.w * SCALE;
        }
    }
    float o[4][4] = {};
    float m_run[4] = {-1e30f, -1e30f, -1e30f, -1e30f};
    float l_run[4] = {0.f, 0.f, 0.f, 0.f};

    for (int j = 0; j <= qt; ++j) {
        __syncthreads();
        int k0 = j * 64;
        {
            int r = tid >> 4, d4 = (tid & 15) * 4;
            for (int rr = r; rr < 64; rr += 16) {
                const float* base = g_qkv + ((size_t)(k0 + rr) * B_ + b) * H3_ + n * 192;
                float4 kv = *(const float4*)(base + 64 + d4);
                KP[rr * 65 + d4 + 0] = kv.x; KP[rr * 65 + d4 + 1] = kv.y;
                KP[rr * 65 + d4 + 2] = kv.z; KP[rr * 65 + d4 + 3] = kv.w;
                float4 vv = *(const float4*)(base + 128 + d4);
                *(float4*)(Vs + rr * 64 + d4) = vv;
            }
        }
        __syncthreads();
        float sacc[4][4] = {};
#pragma unroll 8
        for (int d = 0; d < 64; ++d) {
            float a[4], kr[4];
#pragma unroll
            for (int i = 0; i < 4; i++) a[i]  = Qs[(ty * 4 + i) * 64 + d];
#pragma unroll
            for (int c = 0; c < 4; c++) kr[c] = KP[(tx * 4 + c) * 65 + d];
#pragma unroll
            for (int i = 0; i < 4; i++)
#pragma unroll
                for (int c = 0; c < 4; c++) sacc[i][c] = fmaf(a[i], kr[c], sacc[i][c]);
        }
        if (j == qt) {
#pragma unroll
            for (int i = 0; i < 4; i++)
#pragma unroll
                for (int c = 0; c < 4; c++)
                    if (tx * 4 + c > ty * 4 + i) sacc[i][c] = -1e30f;
        }
        float mx[4], mnew[4], scl[4], rs[4];
#pragma unroll
        for (int i = 0; i < 4; i++) {
            mx[i] = fmaxf(fmaxf(sacc[i][0], sacc[i][1]), fmaxf(sacc[i][2], sacc[i][3]));
            for (int oo = 8; oo; oo >>= 1)
                mx[i] = fmaxf(mx[i], __shfl_xor_sync(0xffffffffu, mx[i], oo));
            mnew[i] = fmaxf(m_run[i], mx[i]);
            scl[i]  = expf(m_run[i] - mnew[i]);
            m_run[i] = mnew[i];
            rs[i] = 0.f;
#pragma unroll
            for (int c = 0; c < 4; c++) {
                sacc[i][c] = expf(sacc[i][c] - mnew[i]);
                rs[i] += sacc[i][c];
            }
            for (int oo = 8; oo; oo >>= 1)
                rs[i] += __shfl_xor_sync(0xffffffffu, rs[i], oo);
            l_run[i] = l_run[i] * scl[i] + rs[i];
#pragma unroll
            for (int c = 0; c < 4; c++) o[i][c] *= scl[i];
        }
        __syncthreads();
#pragma unroll
        for (int i = 0; i < 4; i++)
#pragma unroll
            for (int c = 0; c < 4; c++)
                KP[(ty * 4 + i) * 65 + tx * 4 + c] = sacc[i][c];
        __syncthreads();
#pragma unroll 8
        for (int d = 0; d < 64; ++d) {
            float pi[4], vj[4];
#pragma unroll
            for (int i = 0; i < 4; i++) pi[i] = KP[(ty * 4 + i) * 65 + d];
#pragma unroll
            for (int c = 0; c < 4; c++) vj[c] = Vs[d * 64 + tx * 4 + c];
#pragma unroll
            for (int i = 0; i < 4; i++)
#pragma unroll
                for (int c = 0; c < 4; c++) o[i][c] = fmaf(pi[i], vj[c], o[i][c]);
        }
    }
#pragma unroll
    for (int i = 0; i < 4; i++) {
        float invl = 1.0f / l_run[i];
#pragma unroll
        for (int c = 0; c < 4; c++)
            g_ctx[((size_t)(q0 + ty * 4 + i) * B_ + b) * H_ + n * HD_ + tx * 4 + c] = o[i][c] * invl;
    }
}

// ======================= gate + routing =======================
__global__ void k_gate(const float* __restrict__ gw) {
    int gidx = blockIdx.x * blockDim.x + threadIdx.x;
    int t = gidx >> 5, lane = gidx & 31;
    if (t >= T_) return;
    const float* x = g_ln2 + (size_t)t * H_;
    float s0 = 0, s1 = 0, s2 = 0, s3 = 0;
    for (int h = lane; h < H_; h += 32) {
        float xv = x[h];
        s0 = fmaf(xv, gw[h],          s0);
        s1 = fmaf(xv, gw[H_ + h],     s1);
        s2 = fmaf(xv, gw[2 * H_ + h], s2);
        s3 = fmaf(xv, gw[3 * H_ + h], s3);
    }
    for (int o = 16; o; o >>= 1) {
        s0 += __shfl_xor_sync(0xffffffffu, s0, o);
        s1 += __shfl_xor_sync(0xffffffffu, s1, o);
        s2 += __shfl_xor_sync(0xffffffffu, s2, o);
        s3 += __shfl_xor_sync(0xffffffffu, s3, o);
    }
    if (lane == 0) {
        float l[4] = {s0, s1, s2, s3};
        float mx = fmaxf(fmaxf(l[0], l[1]), fmaxf(l[2], l[3]));
        float ex[4], z = 0.f;
        for (int e = 0; e < 4; e++) { ex[e] = expf(l[e] - mx); z += ex[e]; }
        int best = 0; float bp = ex[0];
        for (int e = 1; e < 4; e++) if (ex[e] > bp) { bp = ex[e]; best = e; }
        g_eidx[t] = best;
        g_prob[t] = bp / z;
    }
}

// single-block counting sort
__global__ void k_route() {
    __shared__ int cnt[E_], fill[E_];
    int tid = threadIdx.x;   // 1024
    if (tid < E_) cnt[tid] = 0;
    __syncthreads();
    for (int t = tid; t < T_; t += 1024) atomicAdd(&cnt[g_eidx[t]], 1);
    __syncthreads();
    if (tid == 0) {
        int a = 0;
        for (int e = 0; e < E_; e++) { fill[e] = a; g_off[e] = a; a += cnt[e]; }
        g_off[E_] = a;
    }
    __syncthreads();
    for (int t = tid; t < T_; t += 1024) {
        int p = atomicAdd(&fill[g_eidx[t]], 1);
        g_perm[p] = t;
    }
}

// ======================= launch =======================
extern "C" void kernel_launch(void* const* d_in, const int* in_sizes, int n_in,
                              void* d_out, int out_size) {
    const float* hidden = (const float*)d_in[0];
    const float* ln1w = (const float*)d_in[2];
    const float* ln1b = (const float*)d_in[3];
    const float* qkvw = (const float*)d_in[4];
    const float* qkvb = (const float*)d_in[5];
    const float* dw   = (const float*)d_in[6];
    const float* db   = (const float*)d_in[7];
    const float* ln2w = (const float*)d_in[8];
    const float* ln2b = (const float*)d_in[9];
    const float* gw   = (const float*)d_in[10];
    const float* w1   = (const float*)d_in[11];
    const float* b1   = (const float*)d_in[12];
    const float* w2   = (const float*)d_in[13];
    const float* b2   = (const float*)d_in[14];
    float* out = (float*)d_out;

    cudaFuncSetAttribute(k_attn, cudaFuncAttributeMaxDynamicSharedMemorySize, 49408);
    cudaFuncSetAttribute((const void*)k_tgemm<0, 768, 1, 4>,
                         cudaFuncAttributeMaxDynamicSharedMemorySize, SMEM_HASLO);
    cudaFuncSetAttribute((const void*)k_tgemm<1, 768, 1, 4>,
                         cudaFuncAttributeMaxDynamicSharedMemorySize, SMEM_HASLO);
    cudaFuncSetAttribute((const void*)k_tgemm<2, 768, FF_, 1>,
                         cudaFuncAttributeMaxDynamicSharedMemorySize, SMEM_NT1);
    cudaFuncSetAttribute((const void*)k_tgemm<3, 3072, H_, 1>,
                         cudaFuncAttributeMaxDynamicSharedMemorySize, SMEM_NT1);

    k_ln1<<<T_, 256>>>(hidden, ln1w, ln1b);
    k_tgemm<0, 768, 1, 4><<<dim3(H3_ / 128, T_ / 128), 256, SMEM_HASLO>>>(qkvw, qkvb, nullptr, nullptr);
    k_attn<<<dim3(S_ / 64, NH_, B_), dim3(16, 16), 49408>>>();
    k_tgemm<1, 768, 1, 4><<<dim3(H_ / 128, T_ / 128), 256, SMEM_HASLO>>>(dw, db, hidden, nullptr);
    k_ln2<<<T_, 256>>>(ln2w, ln2b);
    k_gate<<<T_ / 4, 128>>>(gw);
    k_route<<<1, 1024>>>();
    k_tgemm<2, 768, FF_, 1><<<dim3(FF_ / 128, T_ / 128, E_), 256, SMEM_NT1>>>(w1, b1, nullptr, nullptr);
    k_tgemm<3, 3072, H_, 1><<<dim3(H_ / 128, T_ / 128, E_), 256, SMEM_NT1>>>(w2, b2, nullptr, out);
}

// round 12
// speedup vs baseline: 1.4043x; 1.1050x over previous
#include <cuda_runtime.h>
#include <cuda_bf16.h>
#include <cstdint>
#include <math.h>

#define S_  1024
#define B_  4
#define H_  768
#define NH_ 12
#define HD_ 64
#define FF_ 3072
#define E_  4
#define T_  4096
#define H3_ 2304
#define PITCH 136           // GEMM smem row pitch (words)
#define SLAB  (16 * PITCH)

// ======================= scratch =======================
__device__ float g_ln1[(size_t)T_ * H_];
__device__ float g_qkv[(size_t)T_ * H3_];
__device__ float g_ctx[(size_t)T_ * H_];
__device__ float g_x1 [(size_t)T_ * H_];
__device__ float g_ln2[(size_t)T_ * H_];
__device__ float g_h1 [(size_t)T_ * FF_];
__device__ int   g_eidx[T_];
__device__ float g_prob[T_];
__device__ int   g_perm[T_];
__device__ int   g_off [E_ + 1];

// ======================= mma helpers =======================
__device__ __forceinline__ uint32_t tf32hi(float x) {
    uint32_t h;
    asm("cvt.rna.tf32.f32 %0, %1;" : "=r"(h) : "f"(x));
    return h;
}
__device__ __forceinline__ uint32_t packbf(float a, float b) {
    __nv_bfloat16 x = __float2bfloat16_rn(a), y = __float2bfloat16_rn(b);
    return ((uint32_t)__bfloat16_as_ushort(y) << 16) | __bfloat16_as_ushort(x);
}
// split pair into hi word + lo word
__device__ __forceinline__ void splitpair(float a, float b, uint32_t& hi, uint32_t& lo) {
    __nv_bfloat16 ha = __float2bfloat16_rn(a), hb = __float2bfloat16_rn(b);
    hi = ((uint32_t)__bfloat16_as_ushort(hb) << 16) | __bfloat16_as_ushort(ha);
    lo = packbf(a - __bfloat162float(ha), b - __bfloat162float(hb));
}
#define MMAT(d, a, b) \
    asm volatile("mma.sync.aligned.m16n8k8.row.col.f32.tf32.tf32.f32 " \
        "{%0,%1,%2,%3}, {%4,%5,%6,%7}, {%8,%9}, {%0,%1,%2,%3};" \
        : "+f"((d)[0]), "+f"((d)[1]), "+f"((d)[2]), "+f"((d)[3]) \
        : "r"((a)[0]), "r"((a)[1]), "r"((a)[2]), "r"((a)[3]), "r"((b)[0]), "r"((b)[1]))
#define MMAB(d, a, b) \
    asm volatile("mma.sync.aligned.m16n8k16.row.col.f32.bf16.bf16.f32 " \
        "{%0,%1,%2,%3}, {%4,%5,%6,%7}, {%8,%9}, {%0,%1,%2,%3};" \
        : "+f"((d)[0]), "+f"((d)[1]), "+f"((d)[2]), "+f"((d)[3]) \
        : "r"((a)[0]), "r"((a)[1]), "r"((a)[2]), "r"((a)[3]), "r"((b)[0]), "r"((b)[1]))

// ======================= layernorm =======================
__device__ __forceinline__ void ln_row(const float* __restrict__ x, float* __restrict__ y,
                                       const float* __restrict__ w, const float* __restrict__ b) {
    __shared__ float red[2][8];
    int tid = threadIdx.x;
    float v0 = x[tid], v1 = x[tid + 256], v2 = x[tid + 512];
    float s  = v0 + v1 + v2;
    float ss = v0 * v0 + v1 * v1 + v2 * v2;
    for (int o = 16; o; o >>= 1) {
        s  += __shfl_xor_sync(0xffffffffu, s,  o);
        ss += __shfl_xor_sync(0xffffffffu, ss, o);
    }
    if ((tid & 31) == 0) { red[0][tid >> 5] = s; red[1][tid >> 5] = ss; }
    __syncthreads();
    if (tid < 32) {
        float a = (tid < 8) ? red[0][tid] : 0.f;
        float c = (tid < 8) ? red[1][tid] : 0.f;
        for (int o = 4; o; o >>= 1) {
            a += __shfl_xor_sync(0xffffffffu, a, o);
            c += __shfl_xor_sync(0xffffffffu, c, o);
        }
        if (tid == 0) { red[0][0] = a; red[1][0] = c; }
    }
    __syncthreads();
    float mean = red[0][0] * (1.0f / H_);
    float var  = red[1][0] * (1.0f / H_) - mean * mean;
    float inv  = rsqrtf(var + 1e-5f);
    y[tid]       = (v0 - mean) * inv * w[tid]       + b[tid];
    y[tid + 256] = (v1 - mean) * inv * w[tid + 256] + b[tid + 256];
    y[tid + 512] = (v2 - mean) * inv * w[tid + 512] + b[tid + 512];
}

__global__ void k_ln1(const float* __restrict__ hidden,
                      const float* __restrict__ w, const float* __restrict__ b) {
    ln_row(hidden + (size_t)blockIdx.x * H_, g_ln1 + (size_t)blockIdx.x * H_, w, b);
}
__global__ void k_ln2(const float* __restrict__ w, const float* __restrict__ b) {
    ln_row(g_x1 + (size_t)blockIdx.x * H_, g_ln2 + (size_t)blockIdx.x * H_, w, b);
}

// ======================= tensor-core GEMM (R11, proven) ==========
template<int MODE, int KDIM, int NSTR, int NT>
__global__ void __launch_bounds__(256) k_tgemm(const float* __restrict__ Bsrc,
                                               const float* __restrict__ bias,
                                               const float* __restrict__ extra,
                                               float* __restrict__ outp) {
    constexpr bool TRB = (MODE < 2);
    constexpr bool BF  = (NT == 4);
    constexpr bool HASLO = (NT == 3 || NT == 4);
    constexpr int  BK  = BF ? 32 : 16;
    constexpr int  ACW = BF ? 8 : 4;
    extern __shared__ uint32_t dsm[];
    uint32_t* Ash = dsm;
    uint32_t* Bsh = dsm + 2 * SLAB;
    uint32_t* Asl = HASLO ? dsm + 4 * SLAB : dsm;
    uint32_t* Bsl = HASLO ? dsm + 6 * SLAB : dsm;
    int* sridx = (int*)(dsm + (HASLO ? 8 : 4) * SLAB);

    const int tid = threadIdx.x;
    const int n0 = blockIdx.x * 128;
    const int m0 = blockIdx.y * 128;
    const int e  = (MODE >= 2) ? blockIdx.z : 0;

    int beg = 0, cnt = T_;
    if (MODE >= 2) {
        beg = g_off[e]; cnt = g_off[e + 1] - beg;
        if (m0 >= cnt) return;
    }

    const float* Abase = (MODE == 0) ? g_ln1 : (MODE == 1) ? g_ctx
                        : (MODE == 2) ? g_ln2 : g_h1;
    const float* Bbase = Bsrc;
    if (MODE == 2) Bbase += (size_t)e * H_ * FF_;
    if (MODE == 3) Bbase += (size_t)e * FF_ * H_;

    if (MODE >= 2 && tid < 128)
        sridx[tid] = (m0 + tid < cnt) ? g_perm[beg + m0 + tid] : -1;
    if (MODE >= 2) __syncthreads();

    const int ar = tid >> 2;
    const int ac = tid & 3;
    const int arows[2] = { ar, ar + 64 };
    const float* pA[2];
    bool avA[2];
#pragma unroll
    for (int i = 0; i < 2; i++) {
        int r = arows[i];
        long grow = m0 + r;
        avA[i] = true;
        if (MODE == 2) { int t = sridx[r]; avA[i] = (t >= 0); grow = avA[i] ? t : 0; }
        if (MODE == 3) { avA[i] = (m0 + r < cnt); grow = avA[i] ? (beg + m0 + r) : 0; }
        pA[i] = Abase + (size_t)grow * KDIM + ac * ACW;
    }
    const float* pB[2];
    const float* pBn = nullptr;
    const int bk = tid >> 4;
    const int bc = tid & 15;
    if (TRB) {
#pragma unroll
        for (int i = 0; i < 2; i++)
            pB[i] = Bbase + (size_t)(n0 + arows[i]) * KDIM + ac * ACW;
    } else {
        pBn = Bbase + (size_t)bk * NSTR + n0 + bc * 4;
    }

    float4 ra[2][2], rb[2][2];
    const float4 fz = make_float4(0.f, 0.f, 0.f, 0.f);

    auto storeTF = [&](const float4& v4, uint32_t* dsth, uint32_t* dstl, int row) {
        const float* v = (const float*)&v4;
#pragma unroll
        for (int jj = 0; jj < 4; jj++) {
            int j = (jj + ac) & 3;
            uint32_t h = tf32hi(v[j]);
            dsth[(ac * 4 + j) * PITCH + row] = h;
            if (NT == 3)
                dstl[(ac * 4 + j) * PITCH + row] = tf32hi(v[j] - __uint_as_float(h));
        }
    };
    auto storeBF = [&](const float4& lo4, const float4& hi4,
                       uint32_t* dsth, uint32_t* dstl, int row) {
        float f[8] = {lo4.x, lo4.y, lo4.z, lo4.w, hi4.x, hi4.y, hi4.z, hi4.w};
#pragma unroll
        for (int jj = 0; jj < 4; jj++) {
            int jp = (jj + ac) & 3;
            uint32_t hw, lw;
            splitpair(f[2 * jp], f[2 * jp + 1], hw, lw);
            dsth[(ac * 4 + jp) * PITCH + row] = hw;
            dstl[(ac * 4 + jp) * PITCH + row] = lw;
        }
    };
    auto storeAll = [&](int buf) {
        uint32_t* Ah = Ash + buf * SLAB; uint32_t* Al = Asl + buf * SLAB;
        uint32_t* Bh = Bsh + buf * SLAB; uint32_t* Bl = Bsl + buf * SLAB;
#pragma unroll
        for (int i = 0; i < 2; i++) {
            if (BF) storeBF(ra[i][0], ra[i][1], Ah, Al, arows[i]);
            else    storeTF(ra[i][0], Ah, Al, arows[i]);
        }
        if (TRB) {
#pragma unroll
            for (int i = 0; i < 2; i++) {
                if (BF) storeBF(rb[i][0], rb[i][1], Bh, Bl, arows[i]);
                else    storeTF(rb[i][0], Bh, Bl, arows[i]);
            }
        } else {
#pragma unroll
            for (int i = 0; i < 2; i++) {
                const float* v = (const float*)&rb[i][0];
#pragma unroll
                for (int jj = 0; jj < 4; jj++) {
                    int j = (jj + bc) & 3;
                    Bh[bk * PITCH + bc * 4 + i * 64 + j] = tf32hi(v[j]);
                }
            }
        }
    };
    auto loadSlab = [&](int kn) {
#pragma unroll
        for (int i = 0; i < 2; i++) {
            ra[i][0] = avA[i] ? *(const float4*)(pA[i] + kn) : fz;
            if (BF) ra[i][1] = avA[i] ? *(const float4*)(pA[i] + kn + 4) : fz;
            if (TRB) {
                rb[i][0] = *(const float4*)(pB[i] + kn);
                if (BF) rb[i][1] = *(const float4*)(pB[i] + kn + 4);
            }
        }
        if (!TRB) {
            rb[0][0] = *(const float4*)(pBn + (size_t)kn * NSTR);
            rb[1][0] = *(const float4*)(pBn + (size_t)kn * NSTR + 64);
        }
    };

    loadSlab(0);
    storeAll(0);
    __syncthreads();

    const int wid = tid >> 5, lane = tid & 31;
    const int wm = wid >> 2, wn = wid & 3;
    const int fr = lane >> 2;
    const int fc = lane & 3;

    float acc[4][4][4] = {};
    int cur = 0;

    for (int k0 = 0; k0 < KDIM; k0 += BK) {
        const bool more = (k0 + BK) < KDIM;
        if (more) loadSlab(k0 + BK);

        const uint32_t* ah_ = Ash + cur * SLAB;
        const uint32_t* al_ = Asl + cur * SLAB;
        const uint32_t* bh_ = Bsh + cur * SLAB;
        const uint32_t* bl_ = Bsl + cur * SLAB;
#pragma unroll
        for (int ks = 0; ks < 2; ks++) {
            const int kofs = ks * 8;
            uint32_t ahi[4][4], alo[4][4];
#pragma unroll
            for (int mi = 0; mi < 4; mi++) {
                const int mb = wm * 64 + mi * 16 + fr;
                ahi[mi][0] = ah_[(kofs + fc    ) * PITCH + mb    ];
                ahi[mi][1] = ah_[(kofs + fc    ) * PITCH + mb + 8];
                ahi[mi][2] = ah_[(kofs + fc + 4) * PITCH + mb    ];
                ahi[mi][3] = ah_[(kofs + fc + 4) * PITCH + mb + 8];
                if (HASLO) {
                    alo[mi][0] = al_[(kofs + fc    ) * PITCH + mb    ];
                    alo[mi][1] = al_[(kofs + fc    ) * PITCH + mb + 8];
                    alo[mi][2] = al_[(kofs + fc + 4) * PITCH + mb    ];
                    alo[mi][3] = al_[(kofs + fc + 4) * PITCH + mb + 8];
                }
            }
#pragma unroll
            for (int ni = 0; ni < 4; ni++) {
                const int nb = wn * 32 + ni * 8 + fr;
                uint32_t bhi[2], blo[2];
                bhi[0] = bh_[(kofs + fc    ) * PITCH + nb];
                bhi[1] = bh_[(kofs + fc + 4) * PITCH + nb];
                if (HASLO) {
                    blo[0] = bl_[(kofs + fc    ) * PITCH + nb];
                    blo[1] = bl_[(kofs + fc + 4) * PITCH + nb];
                }
#pragma unroll
                for (int mi = 0; mi < 4; mi++) {
                    if (BF) {
                        MMAB(acc[mi][ni], ahi[mi], bhi);
                        MMAB(acc[mi][ni], ahi[mi], blo);
                        MMAB(acc[mi][ni], alo[mi], bhi);
                    } else {
                        MMAT(acc[mi][ni], ahi[mi], bhi);
                        if (NT == 3) {
                            MMAT(acc[mi][ni], ahi[mi], blo);
                            MMAT(acc[mi][ni], alo[mi], bhi);
                        }
                    }
                }
            }
        }
        if (more) {
            storeAll(cur ^ 1);
            __syncthreads();
            cur ^= 1;
        }
    }

#pragma unroll
    for (int mi = 0; mi < 4; mi++) {
#pragma unroll
        for (int half = 0; half < 2; half++) {
            const int rl = wm * 64 + mi * 16 + fr + half * 8;
            bool valid = true;
            int tkn = 0; float pgate = 0.f;
            if (MODE == 2) valid = (m0 + rl) < cnt;
            if (MODE == 3) { tkn = sridx[rl]; valid = (tkn >= 0); if (valid) pgate = g_prob[tkn]; }
            if (!valid) continue;
#pragma unroll
            for (int ni = 0; ni < 4; ni++) {
                const int n = n0 + wn * 32 + ni * 8 + fc * 2;
                const float v0 = acc[mi][ni][half * 2 + 0];
                const float v1 = acc[mi][ni][half * 2 + 1];
                if (MODE == 0) {
                    size_t o = (size_t)(m0 + rl) * H3_ + n;
                    g_qkv[o]     = v0 + bias[n];
                    g_qkv[o + 1] = v1 + bias[n + 1];
                } else if (MODE == 1) {
                    size_t o = (size_t)(m0 + rl) * H_ + n;
                    g_x1[o]     = extra[o]     + v0 + bias[n];
                    g_x1[o + 1] = extra[o + 1] + v1 + bias[n + 1];
                } else if (MODE == 2) {
                    size_t o = (size_t)(beg + m0 + rl) * FF_ + n;
                    float x0 = v0 + bias[(size_t)e * FF_ + n];
                    float x1 = v1 + bias[(size_t)e * FF_ + n + 1];
                    g_h1[o]     = 0.5f * x0 * (1.0f + erff(x0 * 0.70710678118654752f));
                    g_h1[o + 1] = 0.5f * x1 * (1.0f + erff(x1 * 0.70710678118654752f));
                } else {
                    size_t o = (size_t)tkn * H_ + n;
                    outp[o]     = g_x1[o]     + pgate * (v0 + bias[(size_t)e * H_ + n]);
                    outp[o + 1] = g_x1[o + 1] + pgate * (v1 + bias[(size_t)e * H_ + n + 1]);
                }
            }
        }
    }
}

#define SMEM_HASLO ((8 * SLAB) * 4 + 512)
#define SMEM_NT1   ((4 * SLAB) * 4 + 512)

// ======================= tensor-core causal flash attention =======================
// Q-tile 128, K-tile 64, 8 warps; warp w owns S rows [w*16, w*16+16).
// S = Q*K^T via bf16-3; softmax in-warp; P reused in-registers as PV A-frags; PV bf16-3.
// smem (words): Khi 2304 | Klo 2304 | Vthi 2304 | Vtlo 2304 | scr 64*68=4352  => 54272 B
#define KP_ 72
#define ATT_SMEM ((4 * 2304 + 64 * 68) * 4)
__global__ void __launch_bounds__(256) k_attn() {
    extern __shared__ uint32_t asmem[];
    uint32_t* Khi  = asmem;
    uint32_t* Klo  = Khi + 2304;
    uint32_t* Vthi = Klo + 2304;
    uint32_t* Vtlo = Vthi + 2304;
    float*    scr  = (float*)(Vtlo + 2304);   // [64][68]

    const int qt = blockIdx.x, hn = blockIdx.y, b = blockIdx.z;
    const int tid = threadIdx.x;
    const int wid = tid >> 5, lane = tid & 31;
    const int fr = lane >> 2, fc = lane & 3;
    const int q0 = qt * 128;

    // ---- Q -> registers (scaled 0.125, bf16 hi/lo packed pairs) ----
    uint32_t qhi[4][4], qlo[4][4];
#pragma unroll
    for (int g = 0; g < 4; g++) {
#pragma unroll
        for (int part = 0; part < 4; part++) {
            int row = q0 + wid * 16 + fr + ((part & 1) ? 8 : 0);
            int kw  = g * 8 + fc + ((part & 2) ? 4 : 0);
            const float* p = g_qkv + ((size_t)row * B_ + b) * H3_ + hn * 192 + kw * 2;
            splitpair(p[0] * 0.125f, p[1] * 0.125f, qhi[g][part], qlo[g][part]);
        }
    }

    float m_run[2] = { -1e30f, -1e30f };
    float l_run[2] = { 0.f, 0.f };
    float O[8][4] = {};

    const int jmax = 2 * qt + 1;
    for (int j = 0; j <= jmax; ++j) {
        const int k0 = j * 64;
        // ---- store K (packed hi/lo) + V (raw fp32 scratch) ----
        {
            const int r = tid >> 2, c4 = tid & 3;
            const float* kp = g_qkv + ((size_t)(k0 + r) * B_ + b) * H3_ + hn * 192 + 64 + c4 * 16;
            const float* vp = kp + 64;
#pragma unroll
            for (int i = 0; i < 4; i++) {
                int ii = (i + c4) & 3;                    // stagger
                float4 kv = *(const float4*)(kp + ii * 4);
                int kw = c4 * 8 + ii * 2;
                uint32_t h0, l0, h1, l1;
                splitpair(kv.x, kv.y, h0, l0);
                splitpair(kv.z, kv.w, h1, l1);
                Khi[(kw    ) * KP_ + r] = h0; Klo[(kw    ) * KP_ + r] = l0;
                Khi[(kw + 1) * KP_ + r] = h1; Klo[(kw + 1) * KP_ + r] = l1;
                float4 vv = *(const float4*)(vp + ii * 4);
                *(float4*)&scr[r * 68 + c4 * 16 + ii * 4] = vv;
            }
        }
        __syncthreads();
        // ---- pack V^T hi/lo: word (kw=key-pair, hdrow) ----
#pragma unroll
        for (int i = 0; i < 8; i++) {
            int idx = tid + i * 256;        // 0..2047
            int kw = idx >> 6, hr = idx & 63;
            float v0 = scr[(2 * kw    ) * 68 + hr];
            float v1 = scr[(2 * kw + 1) * 68 + hr];
            uint32_t hw, lw;
            splitpair(v0, v1, hw, lw);
            Vthi[kw * KP_ + hr] = hw;
            Vtlo[kw * KP_ + hr] = lw;
        }
        // ---- S = Q*K^T (bf16-3) ----
        float sacc[8][4] = {};
#pragma unroll
        for (int g = 0; g < 4; g++) {
#pragma unroll
            for (int ni = 0; ni < 8; ni++) {
                const int nb = ni * 8 + fr;
                uint32_t bhi[2], blo[2];
                bhi[0] = Khi[(g * 8 + fc    ) * KP_ + nb];
                bhi[1] = Khi[(g * 8 + fc + 4) * KP_ + nb];
                blo[0] = Klo[(g * 8 + fc    ) * KP_ + nb];
                blo[1] = Klo[(g * 8 + fc + 4) * KP_ + nb];
                MMAB(sacc[ni], qhi[g], bhi);
                MMAB(sacc[ni], qhi[g], blo);
                MMAB(sacc[ni], qlo[g], bhi);
            }
        }
        __syncthreads();   // Vt fully written; Ksm/scr reads done -> next stores safe
        // ---- causal mask (only diag tiles) ----
        if (j >= 2 * qt) {
#pragma unroll
            for (int ni = 0; ni < 8; ni++)
#pragma unroll
                for (int c = 0; c < 4; c++) {
                    int key = k0 + ni * 8 + fc * 2 + (c & 1);
                    int qrow = q0 + wid * 16 + fr + ((c & 2) ? 8 : 0);
                    if (key > qrow) sacc[ni][c] = -1e30f;
                }
        }
        // ---- online softmax (per half-row) ----
#pragma unroll
        for (int h = 0; h < 2; h++) {
            float mx = -1e30f;
#pragma unroll
            for (int ni = 0; ni < 8; ni++)
                mx = fmaxf(mx, fmaxf(sacc[ni][h * 2], sacc[ni][h * 2 + 1]));
            mx = fmaxf(mx, __shfl_xor_sync(0xffffffffu, mx, 1));
            mx = fmaxf(mx, __shfl_xor_sync(0xffffffffu, mx, 2));
            float mnew = fmaxf(m_run[h], mx);
            float sc = expf(m_run[h] - mnew);
            m_run[h] = mnew;
            float rs = 0.f;
#pragma unroll
            for (int ni = 0; ni < 8; ni++) {
                sacc[ni][h * 2]     = expf(sacc[ni][h * 2]     - mnew);
                sacc[ni][h * 2 + 1] = expf(sacc[ni][h * 2 + 1] - mnew);
                rs += sacc[ni][h * 2] + sacc[ni][h * 2 + 1];
            }
            rs += __shfl_xor_sync(0xffffffffu, rs, 1);
            rs += __shfl_xor_sync(0xffffffffu, rs, 2);
            l_run[h] = l_run[h] * sc + rs;
#pragma unroll
            for (int ni = 0; ni < 8; ni++) {
                O[ni][h * 2]     *= sc;
                O[ni][h * 2 + 1] *= sc;
            }
        }
        // ---- PV (P stays in registers as A-frags; bf16-3) ----
#pragma unroll
        for (int g = 0; g < 4; g++) {
            uint32_t phi[4], plo[4];
            splitpair(sacc[2 * g    ][0], sacc[2 * g    ][1], phi[0], plo[0]);
            splitpair(sacc[2 * g    ][2], sacc[2 * g    ][3], phi[1], plo[1]);
            splitpair(sacc[2 * g + 1][0], sacc[2 * g + 1][1], phi[2], plo[2]);
            splitpair(sacc[2 * g + 1][2], sacc[2 * g + 1][3], phi[3], plo[3]);
#pragma unroll
            for (int ni = 0; ni < 8; ni++) {
                const int nb = ni * 8 + fr;
                uint32_t bhi[2], blo[2];
                bhi[0] = Vthi[(g * 8 + fc    ) * KP_ + nb];
                bhi[1] = Vthi[(g * 8 + fc + 4) * KP_ + nb];
                blo[0] = Vtlo[(g * 8 + fc    ) * KP_ + nb];
                blo[1] = Vtlo[(g * 8 + fc + 4) * KP_ + nb];
                MMAB(O[ni], phi, bhi);
                MMAB(O[ni], phi, blo);
                MMAB(O[ni], plo, bhi);
            }
        }
    }
    // ---- epilogue ----
#pragma unroll
    for (int h = 0; h < 2; h++) {
        float invl = 1.0f / l_run[h];
        int token = q0 + wid * 16 + fr + h * 8;
#pragma unroll
        for (int ni = 0; ni < 8; ni++) {
            size_t o = ((size_t)token * B_ + b) * H_ + hn * HD_ + ni * 8 + fc * 2;
            g_ctx[o]     = O[ni][h * 2]     * invl;
            g_ctx[o + 1] = O[ni][h * 2 + 1] * invl;
        }
    }
}

// ======================= gate + routing =======================
__global__ void k_gate(const float* __restrict__ gw) {
    int gidx = blockIdx.x * blockDim.x + threadIdx.x;
    int t = gidx >> 5, lane = gidx & 31;
    if (t >= T_) return;
    const float* x = g_ln2 + (size_t)t * H_;
    float s0 = 0, s1 = 0, s2 = 0, s3 = 0;
    for (int h = lane; h < H_; h += 32) {
        float xv = x[h];
        s0 = fmaf(xv, gw[h],          s0);
        s1 = fmaf(xv, gw[H_ + h],     s1);
        s2 = fmaf(xv, gw[2 * H_ + h], s2);
        s3 = fmaf(xv, gw[3 * H_ + h], s3);
    }
    for (int o = 16; o; o >>= 1) {
        s0 += __shfl_xor_sync(0xffffffffu, s0, o);
        s1 += __shfl_xor_sync(0xffffffffu, s1, o);
        s2 += __shfl_xor_sync(0xffffffffu, s2, o);
        s3 += __shfl_xor_sync(0xffffffffu, s3, o);
    }
    if (lane == 0) {
        float l[4] = {s0, s1, s2, s3};
        float mx = fmaxf(fmaxf(l[0], l[1]), fmaxf(l[2], l[3]));
        float ex[4], z = 0.f;
        for (int e = 0; e < 4; e++) { ex[e] = expf(l[e] - mx); z += ex[e]; }
        int best = 0; float bp = ex[0];
        for (int e = 1; e < 4; e++) if (ex[e] > bp) { bp = ex[e]; best = e; }
        g_eidx[t] = best;
        g_prob[t] = bp / z;
    }
}

__global__ void k_route() {
    __shared__ int cnt[E_], fill[E_];
    int tid = threadIdx.x;
    if (tid < E_) cnt[tid] = 0;
    __syncthreads();
    for (int t = tid; t < T_; t += 1024) atomicAdd(&cnt[g_eidx[t]], 1);
    __syncthreads();
    if (tid == 0) {
        int a = 0;
        for (int e = 0; e < E_; e++) { fill[e] = a; g_off[e] = a; a += cnt[e]; }
        g_off[E_] = a;
    }
    __syncthreads();
    for (int t = tid; t < T_; t += 1024) {
        int p = atomicAdd(&fill[g_eidx[t]], 1);
        g_perm[p] = t;
    }
}

// ======================= launch =======================
extern "C" void kernel_launch(void* const* d_in, const int* in_sizes, int n_in,
                              void* d_out, int out_size) {
    const float* hidden = (const float*)d_in[0];
    const float* ln1w = (const float*)d_in[2];
    const float* ln1b = (const float*)d_in[3];
    const float* qkvw = (const float*)d_in[4];
    const float* qkvb = (const float*)d_in[5];
    const float* dw   = (const float*)d_in[6];
    const float* db   = (const float*)d_in[7];
    const float* ln2w = (const float*)d_in[8];
    const float* ln2b = (const float*)d_in[9];
    const float* gw   = (const float*)d_in[10];
    const float* w1   = (const float*)d_in[11];
    const float* b1   = (const float*)d_in[12];
    const float* w2   = (const float*)d_in[13];
    const float* b2   = (const float*)d_in[14];
    float* out = (float*)d_out;

    cudaFuncSetAttribute(k_attn, cudaFuncAttributeMaxDynamicSharedMemorySize, ATT_SMEM);
    cudaFuncSetAttribute((const void*)k_tgemm<0, 768, 1, 4>,
                         cudaFuncAttributeMaxDynamicSharedMemorySize, SMEM_HASLO);
    cudaFuncSetAttribute((const void*)k_tgemm<1, 768, 1, 4>,
                         cudaFuncAttributeMaxDynamicSharedMemorySize, SMEM_HASLO);
    cudaFuncSetAttribute((const void*)k_tgemm<2, 768, FF_, 1>,
                         cudaFuncAttributeMaxDynamicSharedMemorySize, SMEM_NT1);
    cudaFuncSetAttribute((const void*)k_tgemm<3, 3072, H_, 1>,
                         cudaFuncAttributeMaxDynamicSharedMemorySize, SMEM_NT1);

    k_ln1<<<T_, 256>>>(hidden, ln1w, ln1b);
    k_tgemm<0, 768, 1, 4><<<dim3(H3_ / 128, T_ / 128), 256, SMEM_HASLO>>>(qkvw, qkvb, nullptr, nullptr);
    k_attn<<<dim3(S_ / 128, NH_, B_), 256, ATT_SMEM>>>();
    k_tgemm<1, 768, 1, 4><<<dim3(H_ / 128, T_ / 128), 256, SMEM_HASLO>>>(dw, db, hidden, nullptr);
    k_ln2<<<T_, 256>>>(ln2w, ln2b);
    k_gate<<<T_ / 4, 128>>>(gw);
    k_route<<<1, 1024>>>();
    k_tgemm<2, 768, FF_, 1><<<dim3(FF_ / 128, T_ / 128, E_), 256, SMEM_NT1>>>(w1, b1, nullptr, nullptr);
    k_tgemm<3, 3072, H_, 1><<<dim3(H_ / 128, T_ / 128, E_), 256, SMEM_NT1>>>(w2, b2, nullptr, out);
}

// round 13
// speedup vs baseline: 1.8832x; 1.3410x over previous
#include <cuda_runtime.h>
#include <cuda_bf16.h>
#include <cstdint>
#include <math.h>

#define S_  1024
#define B_  4
#define H_  768
#define NH_ 12
#define HD_ 64
#define FF_ 3072
#define E_  4
#define T_  4096
#define H3_ 2304
#define PITCH 136           // GEMM smem row pitch (words)
#define SLAB  (16 * PITCH)

// ======================= scratch =======================
__device__ float g_ln1[(size_t)T_ * H_];
__device__ float g_qkv[(size_t)T_ * H3_];
__device__ float g_ctx[(size_t)T_ * H_];
__device__ float g_x1 [(size_t)T_ * H_];
__device__ float g_ln2[(size_t)T_ * H_];
__device__ float g_h1 [(size_t)T_ * FF_];
__device__ int   g_eidx[T_];
__device__ float g_prob[T_];
__device__ int   g_perm[T_];
__device__ int   g_off [E_ + 1];

// ======================= mma helpers =======================
__device__ __forceinline__ uint32_t tf32hi(float x) {
    uint32_t h;
    asm("cvt.rna.tf32.f32 %0, %1;" : "=r"(h) : "f"(x));
    return h;
}
__device__ __forceinline__ uint32_t packbf(float a, float b) {
    __nv_bfloat16 x = __float2bfloat16_rn(a), y = __float2bfloat16_rn(b);
    return ((uint32_t)__bfloat16_as_ushort(y) << 16) | __bfloat16_as_ushort(x);
}
__device__ __forceinline__ void splitpair(float a, float b, uint32_t& hi, uint32_t& lo) {
    __nv_bfloat16 ha = __float2bfloat16_rn(a), hb = __float2bfloat16_rn(b);
    hi = ((uint32_t)__bfloat16_as_ushort(hb) << 16) | __bfloat16_as_ushort(ha);
    lo = packbf(a - __bfloat162float(ha), b - __bfloat162float(hb));
}
#define MMAT(d, a, b) \
    asm volatile("mma.sync.aligned.m16n8k8.row.col.f32.tf32.tf32.f32 " \
        "{%0,%1,%2,%3}, {%4,%5,%6,%7}, {%8,%9}, {%0,%1,%2,%3};" \
        : "+f"((d)[0]), "+f"((d)[1]), "+f"((d)[2]), "+f"((d)[3]) \
        : "r"((a)[0]), "r"((a)[1]), "r"((a)[2]), "r"((a)[3]), "r"((b)[0]), "r"((b)[1]))
#define MMAB(d, a, b) \
    asm volatile("mma.sync.aligned.m16n8k16.row.col.f32.bf16.bf16.f32 " \
        "{%0,%1,%2,%3}, {%4,%5,%6,%7}, {%8,%9}, {%0,%1,%2,%3};" \
        : "+f"((d)[0]), "+f"((d)[1]), "+f"((d)[2]), "+f"((d)[3]) \
        : "r"((a)[0]), "r"((a)[1]), "r"((a)[2]), "r"((a)[3]), "r"((b)[0]), "r"((b)[1]))

// ======================= layernorm =======================
__device__ __forceinline__ void ln_row(const float* __restrict__ x, float* __restrict__ y,
                                       const float* __restrict__ w, const float* __restrict__ b) {
    __shared__ float red[2][8];
    int tid = threadIdx.x;
    float v0 = x[tid], v1 = x[tid + 256], v2 = x[tid + 512];
    float s  = v0 + v1 + v2;
    float ss = v0 * v0 + v1 * v1 + v2 * v2;
    for (int o = 16; o; o >>= 1) {
        s  += __shfl_xor_sync(0xffffffffu, s,  o);
        ss += __shfl_xor_sync(0xffffffffu, ss, o);
    }
    if ((tid & 31) == 0) { red[0][tid >> 5] = s; red[1][tid >> 5] = ss; }
    __syncthreads();
    if (tid < 32) {
        float a = (tid < 8) ? red[0][tid] : 0.f;
        float c = (tid < 8) ? red[1][tid] : 0.f;
        for (int o = 4; o; o >>= 1) {
            a += __shfl_xor_sync(0xffffffffu, a, o);
            c += __shfl_xor_sync(0xffffffffu, c, o);
        }
        if (tid == 0) { red[0][0] = a; red[1][0] = c; }
    }
    __syncthreads();
    float mean = red[0][0] * (1.0f / H_);
    float var  = red[1][0] * (1.0f / H_) - mean * mean;
    float inv  = rsqrtf(var + 1e-5f);
    y[tid]       = (v0 - mean) * inv * w[tid]       + b[tid];
    y[tid + 256] = (v1 - mean) * inv * w[tid + 256] + b[tid + 256];
    y[tid + 512] = (v2 - mean) * inv * w[tid + 512] + b[tid + 512];
}

__global__ void k_ln1(const float* __restrict__ hidden,
                      const float* __restrict__ w, const float* __restrict__ b) {
    ln_row(hidden + (size_t)blockIdx.x * H_, g_ln1 + (size_t)blockIdx.x * H_, w, b);
}
__global__ void k_ln2(const float* __restrict__ w, const float* __restrict__ b) {
    ln_row(g_x1 + (size_t)blockIdx.x * H_, g_ln2 + (size_t)blockIdx.x * H_, w, b);
}

// ======================= tensor-core GEMM ==========
// NT==3: tf32 3-term | NT==4: bf16 3-term (QKV/dense) | NT==1: tf32 1-term | NT==5: bf16 1-term (MoE)
// MODE 0/1: B = W[N][K] (transposed store).  MODE 2/3: B = W[K][N] (packed k-pair store for bf16).
template<int MODE, int KDIM, int NSTR, int NT>
__global__ void __launch_bounds__(256) k_tgemm(const float* __restrict__ Bsrc,
                                               const float* __restrict__ bias,
                                               const float* __restrict__ extra,
                                               float* __restrict__ outp) {
    constexpr bool TRB = (MODE < 2);
    constexpr bool BF  = (NT == 4 || NT == 5);
    constexpr bool HASLO = (NT == 3 || NT == 4);
    constexpr int  BK  = BF ? 32 : 16;
    constexpr int  ACW = BF ? 8 : 4;
    extern __shared__ uint32_t dsm[];
    uint32_t* Ash = dsm;
    uint32_t* Bsh = dsm + 2 * SLAB;
    uint32_t* Asl = HASLO ? dsm + 4 * SLAB : dsm;
    uint32_t* Bsl = HASLO ? dsm + 6 * SLAB : dsm;
    int* sridx = (int*)(dsm + (HASLO ? 8 : 4) * SLAB);

    const int tid = threadIdx.x;
    const int n0 = blockIdx.x * 128;
    const int m0 = blockIdx.y * 128;
    const int e  = (MODE >= 2) ? blockIdx.z : 0;

    int beg = 0, cnt = T_;
    if (MODE >= 2) {
        beg = g_off[e]; cnt = g_off[e + 1] - beg;
        if (m0 >= cnt) return;
    }

    const float* Abase = (MODE == 0) ? g_ln1 : (MODE == 1) ? g_ctx
                        : (MODE == 2) ? g_ln2 : g_h1;
    const float* Bbase = Bsrc;
    if (MODE == 2) Bbase += (size_t)e * H_ * FF_;
    if (MODE == 3) Bbase += (size_t)e * FF_ * H_;

    if (MODE >= 2 && tid < 128)
        sridx[tid] = (m0 + tid < cnt) ? g_perm[beg + m0 + tid] : -1;
    if (MODE >= 2) __syncthreads();

    const int ar = tid >> 2;
    const int ac = tid & 3;
    const int arows[2] = { ar, ar + 64 };
    const float* pA[2];
    bool avA[2];
#pragma unroll
    for (int i = 0; i < 2; i++) {
        int r = arows[i];
        long grow = m0 + r;
        avA[i] = true;
        if (MODE == 2) { int t = sridx[r]; avA[i] = (t >= 0); grow = avA[i] ? t : 0; }
        if (MODE == 3) { avA[i] = (m0 + r < cnt); grow = avA[i] ? (beg + m0 + r) : 0; }
        pA[i] = Abase + (size_t)grow * KDIM + ac * ACW;
    }
    const float* pB[2];
    const float* pBn = nullptr;
    const int bk = tid >> 4;          // 0..15
    const int bc = tid & 15;          // 0..15
    if (TRB) {
#pragma unroll
        for (int i = 0; i < 2; i++)
            pB[i] = Bbase + (size_t)(n0 + arows[i]) * KDIM + ac * ACW;
    } else if (BF) {
        pBn = Bbase + (size_t)(2 * bk) * NSTR + n0 + bc * 8;   // k-pair row, 8-col chunk
    } else {
        pBn = Bbase + (size_t)bk * NSTR + n0 + bc * 4;
    }

    float4 ra[2][2], rb[2][2];
    const float4 fz = make_float4(0.f, 0.f, 0.f, 0.f);

    auto storeTF = [&](const float4& v4, uint32_t* dsth, uint32_t* dstl, int row) {
        const float* v = (const float*)&v4;
#pragma unroll
        for (int jj = 0; jj < 4; jj++) {
            int j = (jj + ac) & 3;
            uint32_t h = tf32hi(v[j]);
            dsth[(ac * 4 + j) * PITCH + row] = h;
            if (NT == 3)
                dstl[(ac * 4 + j) * PITCH + row] = tf32hi(v[j] - __uint_as_float(h));
        }
    };
    auto storeBF = [&](const float4& lo4, const float4& hi4,
                       uint32_t* dsth, uint32_t* dstl, int row) {
        float f[8] = {lo4.x, lo4.y, lo4.z, lo4.w, hi4.x, hi4.y, hi4.z, hi4.w};
#pragma unroll
        for (int jj = 0; jj < 4; jj++) {
            int jp = (jj + ac) & 3;
            if (HASLO) {
                uint32_t hw, lw;
                splitpair(f[2 * jp], f[2 * jp + 1], hw, lw);
                dsth[(ac * 4 + jp) * PITCH + row] = hw;
                dstl[(ac * 4 + jp) * PITCH + row] = lw;
            } else {
                dsth[(ac * 4 + jp) * PITCH + row] = packbf(f[2 * jp], f[2 * jp + 1]);
            }
        }
    };
    auto storeAll = [&](int buf) {
        uint32_t* Ah = Ash + buf * SLAB; uint32_t* Al = Asl + buf * SLAB;
        uint32_t* Bh = Bsh + buf * SLAB; uint32_t* Bl = Bsl + buf * SLAB;
#pragma unroll
        for (int i = 0; i < 2; i++) {
            if (BF) storeBF(ra[i][0], ra[i][1], Ah, Al, arows[i]);
            else    storeTF(ra[i][0], Ah, Al, arows[i]);
        }
        if (TRB) {
#pragma unroll
            for (int i = 0; i < 2; i++) {
                if (BF) storeBF(rb[i][0], rb[i][1], Bh, Bl, arows[i]);
                else    storeTF(rb[i][0], Bh, Bl, arows[i]);
            }
        } else if (BF) {
            // packed k-pair words: word(kw=bk, n) = (B[2bk][n], B[2bk+1][n])
            const float* ev0 = (const float*)&rb[0][0];   // even row, cols 0..3
            const float* od0 = (const float*)&rb[0][1];   // odd  row, cols 0..3
            const float* ev1 = (const float*)&rb[1][0];   // even row, cols 4..7
            const float* od1 = (const float*)&rb[1][1];   // odd  row, cols 4..7
#pragma unroll
            for (int q = 0; q < 4; q++) {
                Bh[bk * PITCH + bc * 8 + q]     = packbf(ev0[q], od0[q]);
                Bh[bk * PITCH + bc * 8 + 4 + q] = packbf(ev1[q], od1[q]);
            }
        } else {
#pragma unroll
            for (int i = 0; i < 2; i++) {
                const float* v = (const float*)&rb[i][0];
#pragma unroll
                for (int jj = 0; jj < 4; jj++) {
                    int j = (jj + bc) & 3;
                    Bh[bk * PITCH + bc * 4 + i * 64 + j] = tf32hi(v[j]);
                }
            }
        }
    };
    auto loadSlab = [&](int kn) {
#pragma unroll
        for (int i = 0; i < 2; i++) {
            ra[i][0] = avA[i] ? *(const float4*)(pA[i] + kn) : fz;
            if (BF) ra[i][1] = avA[i] ? *(const float4*)(pA[i] + kn + 4) : fz;
            if (TRB) {
                rb[i][0] = *(const float4*)(pB[i] + kn);
                if (BF) rb[i][1] = *(const float4*)(pB[i] + kn + 4);
            }
        }
        if (!TRB) {
            if (BF) {
                rb[0][0] = *(const float4*)(pBn + (size_t)kn * NSTR);
                rb[0][1] = *(const float4*)(pBn + (size_t)(kn + 1) * NSTR);
                rb[1][0] = *(const float4*)(pBn + (size_t)kn * NSTR + 4);
                rb[1][1] = *(const float4*)(pBn + (size_t)(kn + 1) * NSTR + 4);
            } else {
                rb[0][0] = *(const float4*)(pBn + (size_t)kn * NSTR);
                rb[1][0] = *(const float4*)(pBn + (size_t)kn * NSTR + 64);
            }
        }
    };

    loadSlab(0);
    storeAll(0);
    __syncthreads();

    const int wid = tid >> 5, lane = tid & 31;
    const int wm = wid >> 2, wn = wid & 3;
    const int fr = lane >> 2;
    const int fc = lane & 3;

    float acc[4][4][4] = {};
    int cur = 0;

    for (int k0 = 0; k0 < KDIM; k0 += BK) {
        const bool more = (k0 + BK) < KDIM;
        if (more) loadSlab(k0 + BK);

        const uint32_t* ah_ = Ash + cur * SLAB;
        const uint32_t* al_ = Asl + cur * SLAB;
        const uint32_t* bh_ = Bsh + cur * SLAB;
        const uint32_t* bl_ = Bsl + cur * SLAB;
#pragma unroll
        for (int ks = 0; ks < 2; ks++) {
            const int kofs = ks * 8;
            uint32_t ahi[4][4], alo[4][4];
#pragma unroll
            for (int mi = 0; mi < 4; mi++) {
                const int mb = wm * 64 + mi * 16 + fr;
                ahi[mi][0] = ah_[(kofs + fc    ) * PITCH + mb    ];
                ahi[mi][1] = ah_[(kofs + fc    ) * PITCH + mb + 8];
                ahi[mi][2] = ah_[(kofs + fc + 4) * PITCH + mb    ];
                ahi[mi][3] = ah_[(kofs + fc + 4) * PITCH + mb + 8];
                if (HASLO) {
                    alo[mi][0] = al_[(kofs + fc    ) * PITCH + mb    ];
                    alo[mi][1] = al_[(kofs + fc    ) * PITCH + mb + 8];
                    alo[mi][2] = al_[(kofs + fc + 4) * PITCH + mb    ];
                    alo[mi][3] = al_[(kofs + fc + 4) * PITCH + mb + 8];
                }
            }
#pragma unroll
            for (int ni = 0; ni < 4; ni++) {
                const int nb = wn * 32 + ni * 8 + fr;
                uint32_t bhi[2], blo[2];
                bhi[0] = bh_[(kofs + fc    ) * PITCH + nb];
                bhi[1] = bh_[(kofs + fc + 4) * PITCH + nb];
                if (HASLO) {
                    blo[0] = bl_[(kofs + fc    ) * PITCH + nb];
                    blo[1] = bl_[(kofs + fc + 4) * PITCH + nb];
                }
#pragma unroll
                for (int mi = 0; mi < 4; mi++) {
                    if (BF) {
                        MMAB(acc[mi][ni], ahi[mi], bhi);
                        if (HASLO) {
                            MMAB(acc[mi][ni], ahi[mi], blo);
                            MMAB(acc[mi][ni], alo[mi], bhi);
                        }
                    } else {
                        MMAT(acc[mi][ni], ahi[mi], bhi);
                        if (NT == 3) {
                            MMAT(acc[mi][ni], ahi[mi], blo);
                            MMAT(acc[mi][ni], alo[mi], bhi);
                        }
                    }
                }
            }
        }
        if (more) {
            storeAll(cur ^ 1);
            __syncthreads();
            cur ^= 1;
        }
    }

#pragma unroll
    for (int mi = 0; mi < 4; mi++) {
#pragma unroll
        for (int half = 0; half < 2; half++) {
            const int rl = wm * 64 + mi * 16 + fr + half * 8;
            bool valid = true;
            int tkn = 0; float pgate = 0.f;
            if (MODE == 2) valid = (m0 + rl) < cnt;
            if (MODE == 3) { tkn = sridx[rl]; valid = (tkn >= 0); if (valid) pgate = g_prob[tkn]; }
            if (!valid) continue;
#pragma unroll
            for (int ni = 0; ni < 4; ni++) {
                const int n = n0 + wn * 32 + ni * 8 + fc * 2;
                const float v0 = acc[mi][ni][half * 2 + 0];
                const float v1 = acc[mi][ni][half * 2 + 1];
                if (MODE == 0) {
                    size_t o = (size_t)(m0 + rl) * H3_ + n;
                    g_qkv[o]     = v0 + bias[n];
                    g_qkv[o + 1] = v1 + bias[n + 1];
                } else if (MODE == 1) {
                    size_t o = (size_t)(m0 + rl) * H_ + n;
                    g_x1[o]     = extra[o]     + v0 + bias[n];
                    g_x1[o + 1] = extra[o + 1] + v1 + bias[n + 1];
                } else if (MODE == 2) {
                    size_t o = (size_t)(beg + m0 + rl) * FF_ + n;
                    float x0 = v0 + bias[(size_t)e * FF_ + n];
                    float x1 = v1 + bias[(size_t)e * FF_ + n + 1];
                    g_h1[o]     = 0.5f * x0 * (1.0f + erff(x0 * 0.70710678118654752f));
                    g_h1[o + 1] = 0.5f * x1 * (1.0f + erff(x1 * 0.70710678118654752f));
                } else {
                    size_t o = (size_t)tkn * H_ + n;
                    outp[o]     = g_x1[o]     + pgate * (v0 + bias[(size_t)e * H_ + n]);
                    outp[o + 1] = g_x1[o + 1] + pgate * (v1 + bias[(size_t)e * H_ + n + 1]);
                }
            }
        }
    }
}

#define SMEM_HASLO ((8 * SLAB) * 4 + 512)
#define SMEM_NT1   ((4 * SLAB) * 4 + 512)

// ======================= tensor-core causal flash attention (R12, proven) =======================
#define KP_ 72
#define ATT_SMEM ((4 * 2304 + 64 * 68) * 4)
__global__ void __launch_bounds__(256) k_attn() {
    extern __shared__ uint32_t asmem[];
    uint32_t* Khi  = asmem;
    uint32_t* Klo  = Khi + 2304;
    uint32_t* Vthi = Klo + 2304;
    uint32_t* Vtlo = Vthi + 2304;
    float*    scr  = (float*)(Vtlo + 2304);

    const int qt = blockIdx.x, hn = blockIdx.y, b = blockIdx.z;
    const int tid = threadIdx.x;
    const int wid = tid >> 5, lane = tid & 31;
    const int fr = lane >> 2, fc = lane & 3;
    const int q0 = qt * 128;

    uint32_t qhi[4][4], qlo[4][4];
#pragma unroll
    for (int g = 0; g < 4; g++) {
#pragma unroll
        for (int part = 0; part < 4; part++) {
            int row = q0 + wid * 16 + fr + ((part & 1) ? 8 : 0);
            int kw  = g * 8 + fc + ((part & 2) ? 4 : 0);
            const float* p = g_qkv + ((size_t)row * B_ + b) * H3_ + hn * 192 + kw * 2;
            splitpair(p[0] * 0.125f, p[1] * 0.125f, qhi[g][part], qlo[g][part]);
        }
    }

    float m_run[2] = { -1e30f, -1e30f };
    float l_run[2] = { 0.f, 0.f };
    float O[8][4] = {};

    const int jmax = 2 * qt + 1;
    for (int j = 0; j <= jmax; ++j) {
        const int k0 = j * 64;
        {
            const int r = tid >> 2, c4 = tid & 3;
            const float* kp = g_qkv + ((size_t)(k0 + r) * B_ + b) * H3_ + hn * 192 + 64 + c4 * 16;
            const float* vp = kp + 64;
#pragma unroll
            for (int i = 0; i < 4; i++) {
                int ii = (i + c4) & 3;
                float4 kv = *(const float4*)(kp + ii * 4);
                int kw = c4 * 8 + ii * 2;
                uint32_t h0, l0, h1, l1;
                splitpair(kv.x, kv.y, h0, l0);
                splitpair(kv.z, kv.w, h1, l1);
                Khi[(kw    ) * KP_ + r] = h0; Klo[(kw    ) * KP_ + r] = l0;
                Khi[(kw + 1) * KP_ + r] = h1; Klo[(kw + 1) * KP_ + r] = l1;
                float4 vv = *(const float4*)(vp + ii * 4);
                *(float4*)&scr[r * 68 + c4 * 16 + ii * 4] = vv;
            }
        }
        __syncthreads();
#pragma unroll
        for (int i = 0; i < 8; i++) {
            int idx = tid + i * 256;
            int kw = idx >> 6, hr = idx & 63;
            float v0 = scr[(2 * kw    ) * 68 + hr];
            float v1 = scr[(2 * kw + 1) * 68 + hr];
            uint32_t hw, lw;
            splitpair(v0, v1, hw, lw);
            Vthi[kw * KP_ + hr] = hw;
            Vtlo[kw * KP_ + hr] = lw;
        }
        float sacc[8][4] = {};
#pragma unroll
        for (int g = 0; g < 4; g++) {
#pragma unroll
            for (int ni = 0; ni < 8; ni++) {
                const int nb = ni * 8 + fr;
                uint32_t bhi[2], blo[2];
                bhi[0] = Khi[(g * 8 + fc    ) * KP_ + nb];
                bhi[1] = Khi[(g * 8 + fc + 4) * KP_ + nb];
                blo[0] = Klo[(g * 8 + fc    ) * KP_ + nb];
                blo[1] = Klo[(g * 8 + fc + 4) * KP_ + nb];
                MMAB(sacc[ni], qhi[g], bhi);
                MMAB(sacc[ni], qhi[g], blo);
                MMAB(sacc[ni], qlo[g], bhi);
            }
        }
        __syncthreads();
        if (j >= 2 * qt) {
#pragma unroll
            for (int ni = 0; ni < 8; ni++)
#pragma unroll
                for (int c = 0; c < 4; c++) {
                    int key = k0 + ni * 8 + fc * 2 + (c & 1);
                    int qrow = q0 + wid * 16 + fr + ((c & 2) ? 8 : 0);
                    if (key > qrow) sacc[ni][c] = -1e30f;
                }
        }
#pragma unroll
        for (int h = 0; h < 2; h++) {
            float mx = -1e30f;
#pragma unroll
            for (int ni = 0; ni < 8; ni++)
                mx = fmaxf(mx, fmaxf(sacc[ni][h * 2], sacc[ni][h * 2 + 1]));
            mx = fmaxf(mx, __shfl_xor_sync(0xffffffffu, mx, 1));
            mx = fmaxf(mx, __shfl_xor_sync(0xffffffffu, mx, 2));
            float mnew = fmaxf(m_run[h], mx);
            float sc = expf(m_run[h] - mnew);
            m_run[h] = mnew;
            float rs = 0.f;
#pragma unroll
            for (int ni = 0; ni < 8; ni++) {
                sacc[ni][h * 2]     = expf(sacc[ni][h * 2]     - mnew);
                sacc[ni][h * 2 + 1] = expf(sacc[ni][h * 2 + 1] - mnew);
                rs += sacc[ni][h * 2] + sacc[ni][h * 2 + 1];
            }
            rs += __shfl_xor_sync(0xffffffffu, rs, 1);
            rs += __shfl_xor_sync(0xffffffffu, rs, 2);
            l_run[h] = l_run[h] * sc + rs;
#pragma unroll
            for (int ni = 0; ni < 8; ni++) {
                O[ni][h * 2]     *= sc;
                O[ni][h * 2 + 1] *= sc;
            }
        }
#pragma unroll
        for (int g = 0; g < 4; g++) {
            uint32_t phi[4], plo[4];
            splitpair(sacc[2 * g    ][0], sacc[2 * g    ][1], phi[0], plo[0]);
            splitpair(sacc[2 * g    ][2], sacc[2 * g    ][3], phi[1], plo[1]);
            splitpair(sacc[2 * g + 1][0], sacc[2 * g + 1][1], phi[2], plo[2]);
            splitpair(sacc[2 * g + 1][2], sacc[2 * g + 1][3], phi[3], plo[3]);
#pragma unroll
            for (int ni = 0; ni < 8; ni++) {
                const int nb = ni * 8 + fr;
                uint32_t bhi[2], blo[2];
                bhi[0] = Vthi[(g * 8 + fc    ) * KP_ + nb];
                bhi[1] = Vthi[(g * 8 + fc + 4) * KP_ + nb];
                blo[0] = Vtlo[(g * 8 + fc    ) * KP_ + nb];
                blo[1] = Vtlo[(g * 8 + fc + 4) * KP_ + nb];
                MMAB(O[ni], phi, bhi);
                MMAB(O[ni], phi, blo);
                MMAB(O[ni], plo, bhi);
            }
        }
    }
#pragma unroll
    for (int h = 0; h < 2; h++) {
        float invl = 1.0f / l_run[h];
        int token = q0 + wid * 16 + fr + h * 8;
#pragma unroll
        for (int ni = 0; ni < 8; ni++) {
            size_t o = ((size_t)token * B_ + b) * H_ + hn * HD_ + ni * 8 + fc * 2;
            g_ctx[o]     = O[ni][h * 2]     * invl;
            g_ctx[o + 1] = O[ni][h * 2 + 1] * invl;
        }
    }
}

// ======================= gate + routing =======================
__global__ void k_gate(const float* __restrict__ gw) {
    int gidx = blockIdx.x * blockDim.x + threadIdx.x;
    int t = gidx >> 5, lane = gidx & 31;
    if (t >= T_) return;
    const float* x = g_ln2 + (size_t)t * H_;
    float s0 = 0, s1 = 0, s2 = 0, s3 = 0;
    for (int h = lane; h < H_; h += 32) {
        float xv = x[h];
        s0 = fmaf(xv, gw[h],          s0);
        s1 = fmaf(xv, gw[H_ + h],     s1);
        s2 = fmaf(xv, gw[2 * H_ + h], s2);
        s3 = fmaf(xv, gw[3 * H_ + h], s3);
    }
    for (int o = 16; o; o >>= 1) {
        s0 += __shfl_xor_sync(0xffffffffu, s0, o);
        s1 += __shfl_xor_sync(0xffffffffu, s1, o);
        s2 += __shfl_xor_sync(0xffffffffu, s2, o);
        s3 += __shfl_xor_sync(0xffffffffu, s3, o);
    }
    if (lane == 0) {
        float l[4] = {s0, s1, s2, s3};
        float mx = fmaxf(fmaxf(l[0], l[1]), fmaxf(l[2], l[3]));
        float ex[4], z = 0.f;
        for (int e = 0; e < 4; e++) { ex[e] = expf(l[e] - mx); z += ex[e]; }
        int best = 0; float bp = ex[0];
        for (int e = 1; e < 4; e++) if (ex[e] > bp) { bp = ex[e]; best = e; }
        g_eidx[t] = best;
        g_prob[t] = bp / z;
    }
}

__global__ void k_route() {
    __shared__ int cnt[E_], fill[E_];
    int tid = threadIdx.x;
    if (tid < E_) cnt[tid] = 0;
    __syncthreads();
    for (int t = tid; t < T_; t += 1024) atomicAdd(&cnt[g_eidx[t]], 1);
    __syncthreads();
    if (tid == 0) {
        int a = 0;
        for (int e = 0; e < E_; e++) { fill[e] = a; g_off[e] = a; a += cnt[e]; }
        g_off[E_] = a;
    }
    __syncthreads();
    for (int t = tid; t < T_; t += 1024) {
        int p = atomicAdd(&fill[g_eidx[t]], 1);
        g_perm[p] = t;
    }
}

// ======================= launch =======================
extern "C" void kernel_launch(void* const* d_in, const int* in_sizes, int n_in,
                              void* d_out, int out_size) {
    const float* hidden = (const float*)d_in[0];
    const float* ln1w = (const float*)d_in[2];
    const float* ln1b = (const float*)d_in[3];
    const float* qkvw = (const float*)d_in[4];
    const float* qkvb = (const float*)d_in[5];
    const float* dw   = (const float*)d_in[6];
    const float* db   = (const float*)d_in[7];
    const float* ln2w = (const float*)d_in[8];
    const float* ln2b = (const float*)d_in[9];
    const float* gw   = (const float*)d_in[10];
    const float* w1   = (const float*)d_in[11];
    const float* b1   = (const float*)d_in[12];
    const float* w2   = (const float*)d_in[13];
    const float* b2   = (const float*)d_in[14];
    float* out = (float*)d_out;

    cudaFuncSetAttribute(k_attn, cudaFuncAttributeMaxDynamicSharedMemorySize, ATT_SMEM);
    cudaFuncSetAttribute((const void*)k_tgemm<0, 768, 1, 4>,
                         cudaFuncAttributeMaxDynamicSharedMemorySize, SMEM_HASLO);
    cudaFuncSetAttribute((const void*)k_tgemm<1, 768, 1, 4>,
                         cudaFuncAttributeMaxDynamicSharedMemorySize, SMEM_HASLO);
    cudaFuncSetAttribute((const void*)k_tgemm<2, 768, FF_, 5>,
                         cudaFuncAttributeMaxDynamicSharedMemorySize, SMEM_NT1);
    cudaFuncSetAttribute((const void*)k_tgemm<3, 3072, H_, 5>,
                         cudaFuncAttributeMaxDynamicSharedMemorySize, SMEM_NT1);

    k_ln1<<<T_, 256>>>(hidden, ln1w, ln1b);
    k_tgemm<0, 768, 1, 4><<<dim3(H3_ / 128, T_ / 128), 256, SMEM_HASLO>>>(qkvw, qkvb, nullptr, nullptr);
    k_attn<<<dim3(S_ / 128, NH_, B_), 256, ATT_SMEM>>>();
    k_tgemm<1, 768, 1, 4><<<dim3(H_ / 128, T_ / 128), 256, SMEM_HASLO>>>(dw, db, hidden, nullptr);
    k_ln2<<<T_, 256>>>(ln2w, ln2b);
    k_gate<<<T_ / 4, 128>>>(gw);
    k_route<<<1, 1024>>>();
    k_tgemm<2, 768, FF_, 5><<<dim3(FF_ / 128, T_ / 128, E_), 256, SMEM_NT1>>>(w1, b1, nullptr, nullptr);
    k_tgemm<3, 3072, H_, 5><<<dim3(H_ / 128, T_ / 128, E_), 256, SMEM_NT1>>>(w2, b2, nullptr, out);
}

// round 15
// speedup vs baseline: 1.9027x; 1.0104x over previous
#include <cuda_runtime.h>
#include <cuda_bf16.h>
#include <cstdint>
#include <math.h>

#define S_  1024
#define B_  4
#define H_  768
#define NH_ 12
#define HD_ 64
#define FF_ 3072
#define E_  4
#define T_  4096
#define H3_ 2304
#define PITCH 136           // GEMM smem row pitch (words)
#define SLAB  (16 * PITCH)

// ======================= scratch =======================
__device__ float g_ln1[(size_t)T_ * H_];
__device__ float g_qkv[(size_t)T_ * H3_];
__device__ float g_ctx[(size_t)T_ * H_];
__device__ float g_x1 [(size_t)T_ * H_];
__device__ float g_ln2[(size_t)T_ * H_];
__device__ uint32_t g_h1p[(size_t)T_ * (FF_ / 2)];   // packed bf16 pairs
__device__ int   g_eidx[T_];
__device__ float g_prob[T_];
__device__ int   g_perm[T_];
__device__ int   g_off [E_ + 1];

// ======================= mma helpers =======================
__device__ __forceinline__ uint32_t tf32hi(float x) {
    uint32_t h;
    asm("cvt.rna.tf32.f32 %0, %1;" : "=r"(h) : "f"(x));
    return h;
}
__device__ __forceinline__ uint32_t packbf(float a, float b) {
    __nv_bfloat16 x = __float2bfloat16_rn(a), y = __float2bfloat16_rn(b);
    return ((uint32_t)__bfloat16_as_ushort(y) << 16) | __bfloat16_as_ushort(x);
}
__device__ __forceinline__ void splitpair(float a, float b, uint32_t& hi, uint32_t& lo) {
    __nv_bfloat16 ha = __float2bfloat16_rn(a), hb = __float2bfloat16_rn(b);
    hi = ((uint32_t)__bfloat16_as_ushort(hb) << 16) | __bfloat16_as_ushort(ha);
    lo = packbf(a - __bfloat162float(ha), b - __bfloat162float(hb));
}
#define MMAT(d, a, b) \
    asm volatile("mma.sync.aligned.m16n8k8.row.col.f32.tf32.tf32.f32 " \
        "{%0,%1,%2,%3}, {%4,%5,%6,%7}, {%8,%9}, {%0,%1,%2,%3};" \
        : "+f"((d)[0]), "+f"((d)[1]), "+f"((d)[2]), "+f"((d)[3]) \
        : "r"((a)[0]), "r"((a)[1]), "r"((a)[2]), "r"((a)[3]), "r"((b)[0]), "r"((b)[1]))
#define MMAB(d, a, b) \
    asm volatile("mma.sync.aligned.m16n8k16.row.col.f32.bf16.bf16.f32 " \
        "{%0,%1,%2,%3}, {%4,%5,%6,%7}, {%8,%9}, {%0,%1,%2,%3};" \
        : "+f"((d)[0]), "+f"((d)[1]), "+f"((d)[2]), "+f"((d)[3]) \
        : "r"((a)[0]), "r"((a)[1]), "r"((a)[2]), "r"((a)[3]), "r"((b)[0]), "r"((b)[1]))

// ======================= layernorm =======================
__device__ __forceinline__ void ln_row(const float* __restrict__ x, float* __restrict__ y,
                                       const float* __restrict__ w, const float* __restrict__ b) {
    __shared__ float red[2][8];
    int tid = threadIdx.x;
    float v0 = x[tid], v1 = x[tid + 256], v2 = x[tid + 512];
    float s  = v0 + v1 + v2;
    float ss = v0 * v0 + v1 * v1 + v2 * v2;
    for (int o = 16; o; o >>= 1) {
        s  += __shfl_xor_sync(0xffffffffu, s,  o);
        ss += __shfl_xor_sync(0xffffffffu, ss, o);
    }
    if ((tid & 31) == 0) { red[0][tid >> 5] = s; red[1][tid >> 5] = ss; }
    __syncthreads();
    if (tid < 32) {
        float a = (tid < 8) ? red[0][tid] : 0.f;
        float c = (tid < 8) ? red[1][tid] : 0.f;
        for (int o = 4; o; o >>= 1) {
            a += __shfl_xor_sync(0xffffffffu, a, o);
            c += __shfl_xor_sync(0xffffffffu, c, o);
        }
        if (tid == 0) { red[0][0] = a; red[1][0] = c; }
    }
    __syncthreads();
    float mean = red[0][0] * (1.0f / H_);
    float var  = red[1][0] * (1.0f / H_) - mean * mean;
    float inv  = rsqrtf(var + 1e-5f);
    y[tid]       = (v0 - mean) * inv * w[tid]       + b[tid];
    y[tid + 256] = (v1 - mean) * inv * w[tid + 256] + b[tid + 256];
    y[tid + 512] = (v2 - mean) * inv * w[tid + 512] + b[tid + 512];
}

__global__ void k_ln1(const float* __restrict__ hidden,
                      const float* __restrict__ w, const float* __restrict__ b) {
    ln_row(hidden + (size_t)blockIdx.x * H_, g_ln1 + (size_t)blockIdx.x * H_, w, b);
}
__global__ void k_ln2(const float* __restrict__ w, const float* __restrict__ b) {
    ln_row(g_x1 + (size_t)blockIdx.x * H_, g_ln2 + (size_t)blockIdx.x * H_, w, b);
}

// ======================= tensor-core GEMM ==========
// NT==4: bf16 3-term (QKV/dense) | NT==5: bf16 1-term (MoE) | NT==3/1: tf32 variants
// MODE 0/1: B = W[N][K] (transposed store). MODE 2: B = W[K][N], A = ln2 gathered.
// MODE 3: B = W[K][N], A = g_h1p packed bf16 pairs (compact rows).
template<int MODE, int KDIM, int NSTR, int NT>
__global__ void __launch_bounds__(256, 2) k_tgemm(const float* __restrict__ Bsrc,
                                                  const float* __restrict__ bias,
                                                  const float* __restrict__ extra,
                                                  float* __restrict__ outp) {
    constexpr bool TRB = (MODE < 2);
    constexpr bool BF  = (NT == 4 || NT == 5);
    constexpr bool HASLO = (NT == 3 || NT == 4);
    constexpr bool APACK = (MODE == 3);          // A already packed bf16 pairs
    constexpr int  BK  = BF ? 32 : 16;
    constexpr int  ACW = BF ? 8 : 4;
    extern __shared__ uint32_t dsm[];
    uint32_t* Ash = dsm;
    uint32_t* Bsh = dsm + 2 * SLAB;
    uint32_t* Asl = HASLO ? dsm + 4 * SLAB : dsm;
    uint32_t* Bsl = HASLO ? dsm + 6 * SLAB : dsm;
    int* sridx = (int*)(dsm + (HASLO ? 8 : 4) * SLAB);

    const int tid = threadIdx.x;
    const int n0 = blockIdx.x * 128;
    const int m0 = blockIdx.y * 128;
    const int e  = (MODE >= 2) ? blockIdx.z : 0;

    int beg = 0, cnt = T_;
    if (MODE >= 2) {
        beg = g_off[e]; cnt = g_off[e + 1] - beg;
        if (m0 >= cnt) return;
    }

    const float* Abase = (MODE == 0) ? g_ln1 : (MODE == 1) ? g_ctx : g_ln2;
    const float* Bbase = Bsrc;
    if (MODE == 2) Bbase += (size_t)e * H_ * FF_;
    if (MODE == 3) Bbase += (size_t)e * FF_ * H_;

    if (MODE >= 2 && tid < 128)
        sridx[tid] = (m0 + tid < cnt) ? g_perm[beg + m0 + tid] : -1;
    if (MODE >= 2) __syncthreads();

    const int ar = tid >> 2;
    const int ac = tid & 3;
    const int arows[2] = { ar, ar + 64 };
    const float* pA[2];
    const uint32_t* pAw[2];
    bool avA[2];
#pragma unroll
    for (int i = 0; i < 2; i++) {
        int r = arows[i];
        long grow = m0 + r;
        avA[i] = true;
        if (MODE == 2) { int t = sridx[r]; avA[i] = (t >= 0); grow = avA[i] ? t : 0; }
        if (MODE == 3) { avA[i] = (m0 + r < cnt); grow = avA[i] ? (beg + m0 + r) : 0; }
        if (APACK) pAw[i] = g_h1p + (size_t)grow * (KDIM / 2) + ac * 4;
        else       pA[i]  = Abase + (size_t)grow * KDIM + ac * ACW;
    }
    const float* pB[2];
    const float* pBn = nullptr;
    const int bk = tid >> 4;          // 0..15
    const int bc = tid & 15;          // 0..15
    if (TRB) {
#pragma unroll
        for (int i = 0; i < 2; i++)
            pB[i] = Bbase + (size_t)(n0 + arows[i]) * KDIM + ac * ACW;
    } else if (BF) {
        pBn = Bbase + (size_t)(2 * bk) * NSTR + n0 + bc * 8;   // k-pair row, 8-col chunk
    } else {
        pBn = Bbase + (size_t)bk * NSTR + n0 + bc * 4;
    }

    float4 ra[2][2], rb[2][2];
    uint4 rap[2];
    const float4 fz = make_float4(0.f, 0.f, 0.f, 0.f);
    const uint4  uz = make_uint4(0u, 0u, 0u, 0u);

    auto storeTF = [&](const float4& v4, uint32_t* dsth, uint32_t* dstl, int row) {
        const float* v = (const float*)&v4;
#pragma unroll
        for (int jj = 0; jj < 4; jj++) {
            int j = (jj + ac) & 3;
            uint32_t h = tf32hi(v[j]);
            dsth[(ac * 4 + j) * PITCH + row] = h;
            if (NT == 3)
                dstl[(ac * 4 + j) * PITCH + row] = tf32hi(v[j] - __uint_as_float(h));
        }
    };
    auto storeBF = [&](const float4& lo4, const float4& hi4,
                       uint32_t* dsth, uint32_t* dstl, int row) {
        float f[8] = {lo4.x, lo4.y, lo4.z, lo4.w, hi4.x, hi4.y, hi4.z, hi4.w};
#pragma unroll
        for (int jj = 0; jj < 4; jj++) {
            int jp = (jj + ac) & 3;
            if (HASLO) {
                uint32_t hw, lw;
                splitpair(f[2 * jp], f[2 * jp + 1], hw, lw);
                dsth[(ac * 4 + jp) * PITCH + row] = hw;
                dstl[(ac * 4 + jp) * PITCH + row] = lw;
            } else {
                dsth[(ac * 4 + jp) * PITCH + row] = packbf(f[2 * jp], f[2 * jp + 1]);
            }
        }
    };
    auto storeAll = [&](int buf) {
        uint32_t* Ah = Ash + buf * SLAB; uint32_t* Al = Asl + buf * SLAB;
        uint32_t* Bh = Bsh + buf * SLAB; uint32_t* Bl = Bsl + buf * SLAB;
#pragma unroll
        for (int i = 0; i < 2; i++) {
            if (APACK) {
                const uint32_t* w = (const uint32_t*)&rap[i];
#pragma unroll
                for (int jj = 0; jj < 4; jj++) {
                    int jp = (jj + ac) & 3;
                    Ah[(ac * 4 + jp) * PITCH + arows[i]] = w[jp];
                }
            }
            else if (BF) storeBF(ra[i][0], ra[i][1], Ah, Al, arows[i]);
            else         storeTF(ra[i][0], Ah, Al, arows[i]);
        }
        if (TRB) {
#pragma unroll
            for (int i = 0; i < 2; i++) {
                if (BF) storeBF(rb[i][0], rb[i][1], Bh, Bl, arows[i]);
                else    storeTF(rb[i][0], Bh, Bl, arows[i]);
            }
        } else if (BF) {
            const float* ev0 = (const float*)&rb[0][0];
            const float* od0 = (const float*)&rb[0][1];
            const float* ev1 = (const float*)&rb[1][0];
            const float* od1 = (const float*)&rb[1][1];
#pragma unroll
            for (int q = 0; q < 4; q++) {
                Bh[bk * PITCH + bc * 8 + q]     = packbf(ev0[q], od0[q]);
                Bh[bk * PITCH + bc * 8 + 4 + q] = packbf(ev1[q], od1[q]);
            }
        } else {
#pragma unroll
            for (int i = 0; i < 2; i++) {
                const float* v = (const float*)&rb[i][0];
#pragma unroll
                for (int jj = 0; jj < 4; jj++) {
                    int j = (jj + bc) & 3;
                    Bh[bk * PITCH + bc * 4 + i * 64 + j] = tf32hi(v[j]);
                }
            }
        }
    };
    auto loadSlab = [&](int kn) {
#pragma unroll
        for (int i = 0; i < 2; i++) {
            if (APACK) {
                rap[i] = avA[i] ? *(const uint4*)(pAw[i] + kn / 2) : uz;
            } else {
                ra[i][0] = avA[i] ? *(const float4*)(pA[i] + kn) : fz;
                if (BF) ra[i][1] = avA[i] ? *(const float4*)(pA[i] + kn + 4) : fz;
            }
            if (TRB) {
                rb[i][0] = *(const float4*)(pB[i] + kn);
                if (BF) rb[i][1] = *(const float4*)(pB[i] + kn + 4);
            }
        }
        if (!TRB) {
            if (BF) {
                rb[0][0] = *(const float4*)(pBn + (size_t)kn * NSTR);
                rb[0][1] = *(const float4*)(pBn + (size_t)(kn + 1) * NSTR);
                rb[1][0] = *(const float4*)(pBn + (size_t)kn * NSTR + 4);
                rb[1][1] = *(const float4*)(pBn + (size_t)(kn + 1) * NSTR + 4);
            } else {
                rb[0][0] = *(const float4*)(pBn + (size_t)kn * NSTR);
                rb[1][0] = *(const float4*)(pBn + (size_t)kn * NSTR + 64);
            }
        }
    };

    loadSlab(0);
    storeAll(0);
    __syncthreads();

    const int wid = tid >> 5, lane = tid & 31;
    const int wm = wid >> 2, wn = wid & 3;
    const int fr = lane >> 2;
    const int fc = lane & 3;

    float acc[4][4][4] = {};
    int cur = 0;

    for (int k0 = 0; k0 < KDIM; k0 += BK) {
        const bool more = (k0 + BK) < KDIM;
        if (more) loadSlab(k0 + BK);

        const uint32_t* ah_ = Ash + cur * SLAB;
        const uint32_t* al_ = Asl + cur * SLAB;
        const uint32_t* bh_ = Bsh + cur * SLAB;
        const uint32_t* bl_ = Bsl + cur * SLAB;
#pragma unroll
        for (int ks = 0; ks < 2; ks++) {
            const int kofs = ks * 8;
            uint32_t ahi[4][4], alo[4][4];
#pragma unroll
            for (int mi = 0; mi < 4; mi++) {
                const int mb = wm * 64 + mi * 16 + fr;
                ahi[mi][0] = ah_[(kofs + fc    ) * PITCH + mb    ];
                ahi[mi][1] = ah_[(kofs + fc    ) * PITCH + mb + 8];
                ahi[mi][2] = ah_[(kofs + fc + 4) * PITCH + mb    ];
                ahi[mi][3] = ah_[(kofs + fc + 4) * PITCH + mb + 8];
                if (HASLO) {
                    alo[mi][0] = al_[(kofs + fc    ) * PITCH + mb    ];
                    alo[mi][1] = al_[(kofs + fc    ) * PITCH + mb + 8];
                    alo[mi][2] = al_[(kofs + fc + 4) * PITCH + mb    ];
                    alo[mi][3] = al_[(kofs + fc + 4) * PITCH + mb + 8];
                }
            }
#pragma unroll
            for (int ni = 0; ni < 4; ni++) {
                const int nb = wn * 32 + ni * 8 + fr;
                uint32_t bhi[2], blo[2];
                bhi[0] = bh_[(kofs + fc    ) * PITCH + nb];
                bhi[1] = bh_[(kofs + fc + 4) * PITCH + nb];
                if (HASLO) {
                    blo[0] = bl_[(kofs + fc    ) * PITCH + nb];
                    blo[1] = bl_[(kofs + fc + 4) * PITCH + nb];
                }
#pragma unroll
                for (int mi = 0; mi < 4; mi++) {
                    if (BF) {
                        MMAB(acc[mi][ni], ahi[mi], bhi);
                        if (HASLO) {
                            MMAB(acc[mi][ni], ahi[mi], blo);
                            MMAB(acc[mi][ni], alo[mi], bhi);
                        }
                    } else {
                        MMAT(acc[mi][ni], ahi[mi], bhi);
                        if (NT == 3) {
                            MMAT(acc[mi][ni], ahi[mi], blo);
                            MMAT(acc[mi][ni], alo[mi], bhi);
                        }
                    }
                }
            }
        }
        if (more) {
            storeAll(cur ^ 1);
            __syncthreads();
            cur ^= 1;
        }
    }

#pragma unroll
    for (int mi = 0; mi < 4; mi++) {
#pragma unroll
        for (int half = 0; half < 2; half++) {
            const int rl = wm * 64 + mi * 16 + fr + half * 8;
            bool valid = true;
            int tkn = 0; float pgate = 0.f;
            if (MODE == 2) valid = (m0 + rl) < cnt;
            if (MODE == 3) { tkn = sridx[rl]; valid = (tkn >= 0); if (valid) pgate = g_prob[tkn]; }
            if (!valid) continue;
#pragma unroll
            for (int ni = 0; ni < 4; ni++) {
                const int n = n0 + wn * 32 + ni * 8 + fc * 2;
                const float v0 = acc[mi][ni][half * 2 + 0];
                const float v1 = acc[mi][ni][half * 2 + 1];
                if (MODE == 0) {
                    size_t o = (size_t)(m0 + rl) * H3_ + n;
                    g_qkv[o]     = v0 + bias[n];
                    g_qkv[o + 1] = v1 + bias[n + 1];
                } else if (MODE == 1) {
                    size_t o = (size_t)(m0 + rl) * H_ + n;
                    g_x1[o]     = extra[o]     + v0 + bias[n];
                    g_x1[o + 1] = extra[o + 1] + v1 + bias[n + 1];
                } else if (MODE == 2) {
                    float x0 = v0 + bias[(size_t)e * FF_ + n];
                    float x1 = v1 + bias[(size_t)e * FF_ + n + 1];
                    float g0 = 0.5f * x0 * (1.0f + erff(x0 * 0.70710678118654752f));
                    float g1 = 0.5f * x1 * (1.0f + erff(x1 * 0.70710678118654752f));
                    g_h1p[(size_t)(beg + m0 + rl) * (FF_ / 2) + n / 2] = packbf(g0, g1);
                } else {
                    size_t o = (size_t)tkn * H_ + n;
                    outp[o]     = g_x1[o]     + pgate * (v0 + bias[(size_t)e * H_ + n]);
                    outp[o + 1] = g_x1[o + 1] + pgate * (v1 + bias[(size_t)e * H_ + n + 1]);
                }
            }
        }
    }
}

#define SMEM_HASLO ((8 * SLAB) * 4 + 512)
#define SMEM_NT1   ((4 * SLAB) * 4 + 512)

// ======================= tensor-core causal flash attention (R12, proven) =======================
#define KP_ 72
#define ATT_SMEM ((4 * 2304 + 64 * 68) * 4)
__global__ void __launch_bounds__(256) k_attn() {
    extern __shared__ uint32_t asmem[];
    uint32_t* Khi  = asmem;
    uint32_t* Klo  = Khi + 2304;
    uint32_t* Vthi = Klo + 2304;
    uint32_t* Vtlo = Vthi + 2304;
    float*    scr  = (float*)(Vtlo + 2304);

    const int qt = blockIdx.x, hn = blockIdx.y, b = blockIdx.z;
    const int tid = threadIdx.x;
    const int wid = tid >> 5, lane = tid & 31;
    const int fr = lane >> 2, fc = lane & 3;
    const int q0 = qt * 128;

    uint32_t qhi[4][4], qlo[4][4];
#pragma unroll
    for (int g = 0; g < 4; g++) {
#pragma unroll
        for (int part = 0; part < 4; part++) {
            int row = q0 + wid * 16 + fr + ((part & 1) ? 8 : 0);
            int kw  = g * 8 + fc + ((part & 2) ? 4 : 0);
            const float* p = g_qkv + ((size_t)row * B_ + b) * H3_ + hn * 192 + kw * 2;
            splitpair(p[0] * 0.125f, p[1] * 0.125f, qhi[g][part], qlo[g][part]);
        }
    }

    float m_run[2] = { -1e30f, -1e30f };
    float l_run[2] = { 0.f, 0.f };
    float O[8][4] = {};

    const int jmax = 2 * qt + 1;
    for (int j = 0; j <= jmax; ++j) {
        const int k0 = j * 64;
        {
            const int r = tid >> 2, c4 = tid & 3;
            const float* kp = g_qkv + ((size_t)(k0 + r) * B_ + b) * H3_ + hn * 192 + 64 + c4 * 16;
            const float* vp = kp + 64;
#pragma unroll
            for (int i = 0; i < 4; i++) {
                int ii = (i + c4) & 3;
                float4 kv = *(const float4*)(kp + ii * 4);
                int kw = c4 * 8 + ii * 2;
                uint32_t h0, l0, h1, l1;
                splitpair(kv.x, kv.y, h0, l0);
                splitpair(kv.z, kv.w, h1, l1);
                Khi[(kw    ) * KP_ + r] = h0; Klo[(kw    ) * KP_ + r] = l0;
                Khi[(kw + 1) * KP_ + r] = h1; Klo[(kw + 1) * KP_ + r] = l1;
                float4 vv = *(const float4*)(vp + ii * 4);
                *(float4*)&scr[r * 68 + c4 * 16 + ii * 4] = vv;
            }
        }
        __syncthreads();
#pragma unroll
        for (int i = 0; i < 8; i++) {
            int idx = tid + i * 256;
            int kw = idx >> 6, hr = idx & 63;
            float v0 = scr[(2 * kw    ) * 68 + hr];
            float v1 = scr[(2 * kw + 1) * 68 + hr];
            uint32_t hw, lw;
            splitpair(v0, v1, hw, lw);
            Vthi[kw * KP_ + hr] = hw;
            Vtlo[kw * KP_ + hr] = lw;
        }
        float sacc[8][4] = {};
#pragma unroll
        for (int g = 0; g < 4; g++) {
#pragma unroll
            for (int ni = 0; ni < 8; ni++) {
                const int nb = ni * 8 + fr;
                uint32_t bhi[2], blo[2];
                bhi[0] = Khi[(g * 8 + fc    ) * KP_ + nb];
                bhi[1] = Khi[(g * 8 + fc + 4) * KP_ + nb];
                blo[0] = Klo[(g * 8 + fc    ) * KP_ + nb];
                blo[1] = Klo[(g * 8 + fc + 4) * KP_ + nb];
                MMAB(sacc[ni], qhi[g], bhi);
                MMAB(sacc[ni], qhi[g], blo);
                MMAB(sacc[ni], qlo[g], bhi);
            }
        }
        __syncthreads();
        if (j >= 2 * qt) {
#pragma unroll
            for (int ni = 0; ni < 8; ni++)
#pragma unroll
                for (int c = 0; c < 4; c++) {
                    int key = k0 + ni * 8 + fc * 2 + (c & 1);
                    int qrow = q0 + wid * 16 + fr + ((c & 2) ? 8 : 0);
                    if (key > qrow) sacc[ni][c] = -1e30f;
                }
        }
#pragma unroll
        for (int h = 0; h < 2; h++) {
            float mx = -1e30f;
#pragma unroll
            for (int ni = 0; ni < 8; ni++)
                mx = fmaxf(mx, fmaxf(sacc[ni][h * 2], sacc[ni][h * 2 + 1]));
            mx = fmaxf(mx, __shfl_xor_sync(0xffffffffu, mx, 1));
            mx = fmaxf(mx, __shfl_xor_sync(0xffffffffu, mx, 2));
            float mnew = fmaxf(m_run[h], mx);
            float sc = expf(m_run[h] - mnew);
            m_run[h] = mnew;
            float rs = 0.f;
#pragma unroll
            for (int ni = 0; ni < 8; ni++) {
                sacc[ni][h * 2]     = expf(sacc[ni][h * 2]     - mnew);
                sacc[ni][h * 2 + 1] = expf(sacc[ni][h * 2 + 1] - mnew);
                rs += sacc[ni][h * 2] + sacc[ni][h * 2 + 1];
            }
            rs += __shfl_xor_sync(0xffffffffu, rs, 1);
            rs += __shfl_xor_sync(0xffffffffu, rs, 2);
            l_run[h] = l_run[h] * sc + rs;
#pragma unroll
            for (int ni = 0; ni < 8; ni++) {
                O[ni][h * 2]     *= sc;
                O[ni][h * 2 + 1] *= sc;
            }
        }
#pragma unroll
        for (int g = 0; g < 4; g++) {
            uint32_t phi[4], plo[4];
            splitpair(sacc[2 * g    ][0], sacc[2 * g    ][1], phi[0], plo[0]);
            splitpair(sacc[2 * g    ][2], sacc[2 * g    ][3], phi[1], plo[1]);
            splitpair(sacc[2 * g + 1][0], sacc[2 * g + 1][1], phi[2], plo[2]);
            splitpair(sacc[2 * g + 1][2], sacc[2 * g + 1][3], phi[3], plo[3]);
#pragma unroll
            for (int ni = 0; ni < 8; ni++) {
                const int nb = ni * 8 + fr;
                uint32_t bhi[2], blo[2];
                bhi[0] = Vthi[(g * 8 + fc    ) * KP_ + nb];
                bhi[1] = Vthi[(g * 8 + fc + 4) * KP_ + nb];
                blo[0] = Vtlo[(g * 8 + fc    ) * KP_ + nb];
                blo[1] = Vtlo[(g * 8 + fc + 4) * KP_ + nb];
                MMAB(O[ni], phi, bhi);
                MMAB(O[ni], phi, blo);
                MMAB(O[ni], plo, bhi);
            }
        }
    }
#pragma unroll
    for (int h = 0; h < 2; h++) {
        float invl = 1.0f / l_run[h];
        int token = q0 + wid * 16 + fr + h * 8;
#pragma unroll
        for (int ni = 0; ni < 8; ni++) {
            size_t o = ((size_t)token * B_ + b) * H_ + hn * HD_ + ni * 8 + fc * 2;
            g_ctx[o]     = O[ni][h * 2]     * invl;
            g_ctx[o + 1] = O[ni][h * 2 + 1] * invl;
        }
    }
}

// ======================= gate + routing =======================
__global__ void k_gate(const float* __restrict__ gw) {
    int gidx = blockIdx.x * blockDim.x + threadIdx.x;
    int t = gidx >> 5, lane = gidx & 31;
    if (t >= T_) return;
    const float* x = g_ln2 + (size_t)t * H_;
    float s0 = 0, s1 = 0, s2 = 0, s3 = 0;
    for (int h = lane; h < H_; h += 32) {
        float xv = x[h];
        s0 = fmaf(xv, gw[h],          s0);
        s1 = fmaf(xv, gw[H_ + h],     s1);
        s2 = fmaf(xv, gw[2 * H_ + h], s2);
        s3 = fmaf(xv, gw[3 * H_ + h], s3);
    }
    for (int o = 16; o; o >>= 1) {
        s0 += __shfl_xor_sync(0xffffffffu, s0, o);
        s1 += __shfl_xor_sync(0xffffffffu, s1, o);
        s2 += __shfl_xor_sync(0xffffffffu, s2, o);
        s3 += __shfl_xor_sync(0xffffffffu, s3, o);
    }
    if (lane == 0) {
        float l[4] = {s0, s1, s2, s3};
        float mx = fmaxf(fmaxf(l[0], l[1]), fmaxf(l[2], l[3]));
        float ex[4], z = 0.f;
        for (int e = 0; e < 4; e++) { ex[e] = expf(l[e] - mx); z += ex[e]; }
        int best = 0; float bp = ex[0];
        for (int e = 1; e < 4; e++) if (ex[e] > bp) { bp = ex[e]; best = e; }
        g_eidx[t] = best;
        g_prob[t] = bp / z;
    }
}

__global__ void k_route() {
    __shared__ int cnt[E_], fill[E_];
    int tid = threadIdx.x;
    if (tid < E_) cnt[tid] = 0;
    __syncthreads();
    for (int t = tid; t < T_; t += 1024) atomicAdd(&cnt[g_eidx[t]], 1);
    __syncthreads();
    if (tid == 0) {
        int a = 0;
        for (int e = 0; e < E_; e++) { fill[e] = a; g_off[e] = a; a += cnt[e]; }
        g_off[E_] = a;
    }
    __syncthreads();
    for (int t = tid; t < T_; t += 1024) {
        int p = atomicAdd(&fill[g_eidx[t]], 1);
        g_perm[p] = t;
    }
}

// ======================= launch =======================
extern "C" void kernel_launch(void* const* d_in, const int* in_sizes, int n_in,
                              void* d_out, int out_size) {
    const float* hidden = (const float*)d_in[0];
    const float* ln1w = (const float*)d_in[2];
    const float* ln1b = (const float*)d_in[3];
    const float* qkvw = (const float*)d_in[4];
    const float* qkvb = (const float*)d_in[5];
    const float* dw   = (const float*)d_in[6];
    const float* db   = (const float*)d_in[7];
    const float* ln2w = (const float*)d_in[8];
    const float* ln2b = (const float*)d_in[9];
    const float* gw   = (const float*)d_in[10];
    const float* w1   = (const float*)d_in[11];
    const float* b1   = (const float*)d_in[12];
    const float* w2   = (const float*)d_in[13];
    const float* b2   = (const float*)d_in[14];
    float* out = (float*)d_out;

    cudaFuncSetAttribute(k_attn, cudaFuncAttributeMaxDynamicSharedMemorySize, ATT_SMEM);
    cudaFuncSetAttribute((const void*)k_tgemm<0, 768, 1, 4>,
                         cudaFuncAttributeMaxDynamicSharedMemorySize, SMEM_HASLO);
    cudaFuncSetAttribute((const void*)k_tgemm<1, 768, 1, 4>,
                         cudaFuncAttributeMaxDynamicSharedMemorySize, SMEM_HASLO);
    cudaFuncSetAttribute((const void*)k_tgemm<2, 768, FF_, 5>,
                         cudaFuncAttributeMaxDynamicSharedMemorySize, SMEM_NT1);
    cudaFuncSetAttribute((const void*)k_tgemm<3, 3072, H_, 5>,
                         cudaFuncAttributeMaxDynamicSharedMemorySize, SMEM_NT1);

    k_ln1<<<T_, 256>>>(hidden, ln1w, ln1b);
    k_tgemm<0, 768, 1, 4><<<dim3(H3_ / 128, T_ / 128), 256, SMEM_HASLO>>>(qkvw, qkvb, nullptr, nullptr);
    k_attn<<<dim3(S_ / 128, NH_, B_), 256, ATT_SMEM>>>();
    k_tgemm<1, 768, 1, 4><<<dim3(H_ / 128, T_ / 128), 256, SMEM_HASLO>>>(dw, db, hidden, nullptr);
    k_ln2<<<T_, 256>>>(ln2w, ln2b);
    k_gate<<<T_ / 4, 128>>>(gw);
    k_route<<<1, 1024>>>();
    k_tgemm<2, 768, FF_, 5><<<dim3(FF_ / 128, T_ / 128, E_), 256, SMEM_NT1>>>(w1, b1, nullptr, nullptr);
    k_tgemm<3, 3072, H_, 5><<<dim3(H_ / 128, T_ / 128, E_), 256, SMEM_NT1>>>(w2, b2, nullptr, out);
}